// round 3
// baseline (speedup 1.0000x reference)
#include <cuda_runtime.h>
#include <cstdint>

#define Bn 2
#define CSn 128
#define CDn 128
#define SDn 8
#define SHn 16
#define SWn 16
#define DDn 16
#define DHn 32
#define DWn 32
#define Pn  (DDn*DHn*DWn)      /* 16384 */
#define Gn 8
#define K3n 27
#define CGn 16                 /* CS/G */
#define NOFF (K3n*3*Gn)        /* 648 */
#define KTOT (Gn*K3n*CGn)      /* 3456 */

typedef unsigned long long ull;

// ---------------- f32x2 helpers (FFMA2 — ptxas never emits from C++) -------
__device__ __forceinline__ ull ffma2(ull a, ull b, ull c) {
    ull d;
    asm("fma.rn.f32x2 %0, %1, %2, %3;" : "=l"(d) : "l"(a), "l"(b), "l"(c));
    return d;
}
__device__ __forceinline__ ull dup2(float s) {
    ull d;
    unsigned u = __float_as_uint(s);
    asm("mov.b64 %0, {%1, %1};" : "=l"(d) : "r"(u));
    return d;
}
__device__ __forceinline__ float lo32(ull v) {
    return __uint_as_float((unsigned)(v & 0xffffffffull));
}
__device__ __forceinline__ float hi32(ull v) {
    return __uint_as_float((unsigned)(v >> 32));
}

// -------- device scratch (allocation-free rule: __device__ globals) --------
__device__ float g_src_cl[Bn*SDn*SHn*SWn*CSn];   // [b][z][y][x][c]
__device__ float g_up_cl[Bn*Pn*CSn];             // [b][p][c]
__device__ float g_off[Bn*NOFF*Pn];              // [b][o][p]
__device__ float g_wofft[256*NOFF];              // [c][o]
__device__ float g_ws[KTOT*CDn];                 // [(g*27+tap)*16+cg][o]
__device__ float g_samp[(size_t)Bn*KTOT*Pn];     // [b][k][p]  (453MB)

// -------- prep transposes --------
__global__ void k_transpose_src(const float* __restrict__ src) {
    int i = blockIdx.x * blockDim.x + threadIdx.x;
    const int N = Bn*SDn*SHn*SWn*CSn;
    if (i >= N) return;
    int c = i % CSn;
    int s = (i / CSn) % (SDn*SHn*SWn);
    int b = i / (CSn*SDn*SHn*SWn);
    g_src_cl[i] = src[(b*CSn + c)*(SDn*SHn*SWn) + s];
}

__global__ void k_transpose_woff(const float* __restrict__ w) { // w:[648][256]
    int i = blockIdx.x * blockDim.x + threadIdx.x;
    if (i >= 256*NOFF) return;
    int o = i % NOFF;
    int c = i / NOFF;
    g_wofft[i] = w[o*256 + c];
}

__global__ void k_transpose_wdcn(const float* __restrict__ w) { // w:[o][c][27]
    int i = blockIdx.x * blockDim.x + threadIdx.x;
    if (i >= KTOT*CDn) return;
    int o  = i % CDn;
    int cg = (i / CDn) % CGn;
    int k  = (i / (CDn*CGn)) % K3n;
    int g  = i / (CDn*CGn*K3n);
    g_ws[i] = w[(o*CSn + g*CGn + cg)*K3n + k];
}

// -------- trilinear 2x upsample (half-pixel, edge-clamped == jax resize) ----
__global__ void k_upsample() {
    int bp = blockIdx.x;                 // Bn*Pn blocks
    int b = bp / Pn;
    int p = bp % Pn;
    int d = p >> 10, h = (p >> 5) & 31, w = p & 31;

    float zc = d*0.5f - 0.25f, yc = h*0.5f - 0.25f, xc = w*0.5f - 0.25f;
    int zf = (int)floorf(zc), yf = (int)floorf(yc), xf = (int)floorf(xc);
    float fz = zc - zf, fy = yc - yf, fx = xc - xf;
    int z0 = min(max(zf,     0), SDn-1), z1 = min(max(zf + 1, 0), SDn-1);
    int y0 = min(max(yf,     0), SHn-1), y1 = min(max(yf + 1, 0), SHn-1);
    int x0 = min(max(xf,     0), SWn-1), x1 = min(max(xf + 1, 0), SWn-1);

    const float* base = g_src_cl + (size_t)b * (SDn*SHn*SWn) * CSn;
    int c = threadIdx.x;  // 128

    float v000 = base[(z0*256 + y0*16 + x0)*CSn + c];
    float v001 = base[(z0*256 + y0*16 + x1)*CSn + c];
    float v010 = base[(z0*256 + y1*16 + x0)*CSn + c];
    float v011 = base[(z0*256 + y1*16 + x1)*CSn + c];
    float v100 = base[(z1*256 + y0*16 + x0)*CSn + c];
    float v101 = base[(z1*256 + y0*16 + x1)*CSn + c];
    float v110 = base[(z1*256 + y1*16 + x0)*CSn + c];
    float v111 = base[(z1*256 + y1*16 + x1)*CSn + c];

    float r0 = (1.f-fy)*((1.f-fx)*v000 + fx*v001) + fy*((1.f-fx)*v010 + fx*v011);
    float r1 = (1.f-fy)*((1.f-fx)*v100 + fx*v101) + fy*((1.f-fx)*v110 + fx*v111);
    g_up_cl[((size_t)b*Pn + p)*CSn + c] = (1.f-fz)*r0 + fz*r1;
}

// -------- 1x1 offset conv (unchanged from R2) -------------------------------
__global__ void __launch_bounds__(256) k_offset(const float* __restrict__ dst) {
    __shared__ __align__(16) float cat_s[256*32];     // [c][v] 32KB
    int blk = blockIdx.x;               // Bn*(Pn/32)
    int b  = blk / (Pn/32);
    int p0 = (blk % (Pn/32)) * 32;
    int t = threadIdx.x;

    for (int i = t; i < 128*32; i += 256) {
        int c = i >> 5, v = i & 31;
        cat_s[i] = dst[((size_t)b*CDn + c)*Pn + p0 + v];
    }
    for (int i = t; i < 32*128; i += 256) {
        int v = i >> 7, c = i & 127;
        cat_s[(128 + c)*32 + v] = 2.0f * g_up_cl[((size_t)b*Pn + p0 + v)*CSn + c];
    }
    __syncthreads();

    int og = t >> 3;
    int vg = t & 7;
    int v0 = vg * 4;

    #pragma unroll
    for (int pass = 0; pass < 3; ++pass) {
        int o0 = pass*256 + og*8;
        if (o0 >= NOFF) break;
        ull a[4][4];
        #pragma unroll
        for (int i = 0; i < 4; ++i)
            #pragma unroll
            for (int j = 0; j < 4; ++j) a[i][j] = 0ull;

        #pragma unroll 4
        for (int c = 0; c < 256; ++c) {
            const ulonglong2* wrow = (const ulonglong2*)&g_wofft[c*NOFF + o0];
            ulonglong2 wA = wrow[0];
            ulonglong2 wB = wrow[1];
            float4 sv = *(const float4*)&cat_s[c*32 + v0];
            ull s0 = dup2(sv.x), s1 = dup2(sv.y);
            ull s2 = dup2(sv.z), s3 = dup2(sv.w);
            a[0][0] = ffma2(wA.x, s0, a[0][0]); a[0][1] = ffma2(wA.x, s1, a[0][1]);
            a[0][2] = ffma2(wA.x, s2, a[0][2]); a[0][3] = ffma2(wA.x, s3, a[0][3]);
            a[1][0] = ffma2(wA.y, s0, a[1][0]); a[1][1] = ffma2(wA.y, s1, a[1][1]);
            a[1][2] = ffma2(wA.y, s2, a[1][2]); a[1][3] = ffma2(wA.y, s3, a[1][3]);
            a[2][0] = ffma2(wB.x, s0, a[2][0]); a[2][1] = ffma2(wB.x, s1, a[2][1]);
            a[2][2] = ffma2(wB.x, s2, a[2][2]); a[2][3] = ffma2(wB.x, s3, a[2][3]);
            a[3][0] = ffma2(wB.y, s0, a[3][0]); a[3][1] = ffma2(wB.y, s1, a[3][1]);
            a[3][2] = ffma2(wB.y, s2, a[3][2]); a[3][3] = ffma2(wB.y, s3, a[3][3]);
        }

        #pragma unroll
        for (int op = 0; op < 4; ++op) {
            float4 flo = make_float4(lo32(a[op][0]), lo32(a[op][1]),
                                     lo32(a[op][2]), lo32(a[op][3]));
            float4 fhi = make_float4(hi32(a[op][0]), hi32(a[op][1]),
                                     hi32(a[op][2]), hi32(a[op][3]));
            size_t base = ((size_t)b*NOFF + o0 + op*2)*Pn + p0 + v0;
            *(float4*)&g_off[base]              = flo;
            *(float4*)&g_off[base + (size_t)Pn] = fhi;
        }
    }
}

// -------- deformable trilinear sampling: g_samp[b][k][p] --------------------
// one thread per (b,g,p); loops 27 taps; coord math once; 16 channels/thread.
__global__ void __launch_bounds__(256) k_sample() {
    int blk = blockIdx.x;               // Bn*Gn*(Pn/256) = 1024
    int b = blk >> 9;
    int g = (blk >> 6) & 7;
    int p = (blk & 63) * 256 + threadIdx.x;
    int d = p >> 10, h = (p >> 5) & 31, w = p & 31;

    const float* upg = g_up_cl + (size_t)b*Pn*CSn + g*CGn;
    const size_t offB = (size_t)b*NOFF*Pn + (size_t)(g*K3n)*3*Pn;
    const size_t sampB = ((size_t)b*KTOT + (size_t)g*K3n*CGn)*Pn + p;

    for (int k = 0; k < K3n; ++k) {
        int kz = k/9 - 1, ky = (k/3)%3 - 1, kx = k%3 - 1;
        float z = d + kz + g_off[offB + (size_t)(k*3+0)*Pn + p];
        float y = h + ky + g_off[offB + (size_t)(k*3+1)*Pn + p];
        float x = w + kx + g_off[offB + (size_t)(k*3+2)*Pn + p];

        float z0f = floorf(z), y0f = floorf(y), x0f = floorf(x);
        float fz = z - z0f, fy = y - y0f, fx = x - x0f;
        int z0 = (int)z0f, y0 = (int)y0f, x0 = (int)x0f;

        ull acc[8];
        #pragma unroll
        for (int j = 0; j < 8; ++j) acc[j] = 0ull;

        #pragma unroll
        for (int cnr = 0; cnr < 8; ++cnr) {
            int dz = cnr>>2, dy = (cnr>>1)&1, dx = cnr&1;
            int iz = z0+dz, iy = y0+dy, ix = x0+dx;
            float wt = (dz ? fz : 1.f-fz) * (dy ? fy : 1.f-fy) * (dx ? fx : 1.f-fx);
            bool ok = (iz>=0) & (iz<DDn) & (iy>=0) & (iy<DHn) & (ix>=0) & (ix<DWn);
            wt = ok ? wt : 0.f;
            int ci = min(max(iz,0),DDn-1)*1024 + min(max(iy,0),DHn-1)*32 + min(max(ix,0),DWn-1);
            const ulonglong2* vp = (const ulonglong2*)(upg + (size_t)ci*CSn);
            ulonglong2 v0 = vp[0], v1 = vp[1], v2 = vp[2], v3 = vp[3];
            ull wd = dup2(wt);
            acc[0] = ffma2(v0.x, wd, acc[0]); acc[1] = ffma2(v0.y, wd, acc[1]);
            acc[2] = ffma2(v1.x, wd, acc[2]); acc[3] = ffma2(v1.y, wd, acc[3]);
            acc[4] = ffma2(v2.x, wd, acc[4]); acc[5] = ffma2(v2.y, wd, acc[5]);
            acc[6] = ffma2(v3.x, wd, acc[6]); acc[7] = ffma2(v3.y, wd, acc[7]);
        }

        size_t base = sampB + (size_t)(k*CGn)*Pn;
        #pragma unroll
        for (int j = 0; j < 8; ++j) {
            g_samp[base + (size_t)(2*j  )*Pn] = lo32(acc[j]);
            g_samp[base + (size_t)(2*j+1)*Pn] = hi32(acc[j]);
        }
    }
}

// -------- output GEMM: out[b,o,p] = relu(sum_k ws[k][o]*samp[b][k][p]) ------
// block: 128 o x 128 p, 256 threads. warp owns 16-o slab -> uniform w LDS
// (broadcast). thread: 16 o (8 o-pairs in f32x2) x 4 p. K chunks of 16,
// double-buffered, 1 sync/chunk.
__global__ void __launch_bounds__(256, 2) k_gemm(float* __restrict__ out) {
    __shared__ __align__(16) float ss[2][16][128];   // samp chunk, 16KB
    __shared__ __align__(16) float ws[2][16][128];   // w chunk,    16KB

    int blk = blockIdx.x;          // Bn*(Pn/128) = 256
    int b  = blk >> 7;
    int p0 = (blk & 127) * 128;
    int t  = threadIdx.x;
    int wid = t >> 5, l = t & 31;
    int o0 = wid * 16;
    int pl = l * 4;

    // staging map: row r = t>>4 (0..15), cols c..c+7
    int sr = t >> 4;
    int sc = (t & 15) * 8;
    const size_t sampRow = ((size_t)b*KTOT + sr) * Pn + p0 + sc;

    ull acc[8][4];
    #pragma unroll
    for (int m = 0; m < 8; ++m)
        #pragma unroll
        for (int j = 0; j < 4; ++j) acc[m][j] = 0ull;

    // prologue: stage chunk 0 into buf 0
    {
        const float4* srcS = (const float4*)&g_samp[sampRow];
        *(float4*)&ss[0][sr][sc]   = srcS[0];
        *(float4*)&ss[0][sr][sc+4] = srcS[1];
        const float4* srcW = (const float4*)&g_ws[sr*CDn + sc];
        *(float4*)&ws[0][sr][sc]   = srcW[0];
        *(float4*)&ws[0][sr][sc+4] = srcW[1];
    }
    __syncthreads();

    for (int kc = 0; kc < KTOT/16; ++kc) {
        int cur = kc & 1;
        if (kc + 1 < KTOT/16) {
            int nb = cur ^ 1;
            const float4* srcS = (const float4*)&g_samp[sampRow + (size_t)(kc+1)*16*Pn];
            *(float4*)&ss[nb][sr][sc]   = srcS[0];
            *(float4*)&ss[nb][sr][sc+4] = srcS[1];
            const float4* srcW = (const float4*)&g_ws[((kc+1)*16 + sr)*CDn + sc];
            *(float4*)&ws[nb][sr][sc]   = srcW[0];
            *(float4*)&ws[nb][sr][sc+4] = srcW[1];
        }

        #pragma unroll
        for (int k = 0; k < 16; ++k) {
            const ulonglong2* wr = (const ulonglong2*)&ws[cur][k][o0]; // uniform/warp
            ulonglong2 wa = wr[0], wb = wr[1], wc = wr[2], wd = wr[3];
            float4 sv = *(const float4*)&ss[cur][k][pl];
            ull s0 = dup2(sv.x), s1 = dup2(sv.y), s2 = dup2(sv.z), s3 = dup2(sv.w);
            acc[0][0]=ffma2(wa.x,s0,acc[0][0]); acc[0][1]=ffma2(wa.x,s1,acc[0][1]);
            acc[0][2]=ffma2(wa.x,s2,acc[0][2]); acc[0][3]=ffma2(wa.x,s3,acc[0][3]);
            acc[1][0]=ffma2(wa.y,s0,acc[1][0]); acc[1][1]=ffma2(wa.y,s1,acc[1][1]);
            acc[1][2]=ffma2(wa.y,s2,acc[1][2]); acc[1][3]=ffma2(wa.y,s3,acc[1][3]);
            acc[2][0]=ffma2(wb.x,s0,acc[2][0]); acc[2][1]=ffma2(wb.x,s1,acc[2][1]);
            acc[2][2]=ffma2(wb.x,s2,acc[2][2]); acc[2][3]=ffma2(wb.x,s3,acc[2][3]);
            acc[3][0]=ffma2(wb.y,s0,acc[3][0]); acc[3][1]=ffma2(wb.y,s1,acc[3][1]);
            acc[3][2]=ffma2(wb.y,s2,acc[3][2]); acc[3][3]=ffma2(wb.y,s3,acc[3][3]);
            acc[4][0]=ffma2(wc.x,s0,acc[4][0]); acc[4][1]=ffma2(wc.x,s1,acc[4][1]);
            acc[4][2]=ffma2(wc.x,s2,acc[4][2]); acc[4][3]=ffma2(wc.x,s3,acc[4][3]);
            acc[5][0]=ffma2(wc.y,s0,acc[5][0]); acc[5][1]=ffma2(wc.y,s1,acc[5][1]);
            acc[5][2]=ffma2(wc.y,s2,acc[5][2]); acc[5][3]=ffma2(wc.y,s3,acc[5][3]);
            acc[6][0]=ffma2(wd.x,s0,acc[6][0]); acc[6][1]=ffma2(wd.x,s1,acc[6][1]);
            acc[6][2]=ffma2(wd.x,s2,acc[6][2]); acc[6][3]=ffma2(wd.x,s3,acc[6][3]);
            acc[7][0]=ffma2(wd.y,s0,acc[7][0]); acc[7][1]=ffma2(wd.y,s1,acc[7][1]);
            acc[7][2]=ffma2(wd.y,s2,acc[7][2]); acc[7][3]=ffma2(wd.y,s3,acc[7][3]);
        }
        __syncthreads();
    }

    // ReLU + write: o-pair m -> rows o0+2m, o0+2m+1; 4 contiguous p each
    #pragma unroll
    for (int m = 0; m < 8; ++m) {
        float4 flo = make_float4(fmaxf(lo32(acc[m][0]),0.f), fmaxf(lo32(acc[m][1]),0.f),
                                 fmaxf(lo32(acc[m][2]),0.f), fmaxf(lo32(acc[m][3]),0.f));
        float4 fhi = make_float4(fmaxf(hi32(acc[m][0]),0.f), fmaxf(hi32(acc[m][1]),0.f),
                                 fmaxf(hi32(acc[m][2]),0.f), fmaxf(hi32(acc[m][3]),0.f));
        size_t base = ((size_t)b*CDn + o0 + 2*m)*Pn + p0 + pl;
        *(float4*)&out[base]              = flo;
        *(float4*)&out[base + (size_t)Pn] = fhi;
    }
}

extern "C" void kernel_launch(void* const* d_in, const int* in_sizes, int n_in,
                              void* d_out, int out_size) {
    const float* src  = (const float*)d_in[0];   // feat_1x_src [2,128,8,16,16]
    const float* dst  = (const float*)d_in[1];   // feat_2x_dst [2,128,16,32,32]
    const float* woff = (const float*)d_in[2];   // w_offset [648,256]
    const float* wdcn = (const float*)d_in[3];   // w_dcn [128,128,3,3,3]
    float* out = (float*)d_out;

    k_transpose_src <<<(Bn*SDn*SHn*SWn*CSn + 255)/256, 256>>>(src);
    k_transpose_woff<<<(256*NOFF + 255)/256, 256>>>(woff);
    k_transpose_wdcn<<<(KTOT*CDn + 255)/256, 256>>>(wdcn);
    k_upsample      <<<Bn*Pn, 128>>>();
    k_offset        <<<Bn*(Pn/32), 256>>>(dst);
    k_sample        <<<Bn*Gn*(Pn/256), 256>>>();
    k_gemm          <<<Bn*(Pn/128), 256>>>(out);
}

// round 4
// speedup vs baseline: 1.0987x; 1.0987x over previous
#include <cuda_runtime.h>
#include <cstdint>

#define Bn 2
#define CSn 128
#define CDn 128
#define SDn 8
#define SHn 16
#define SWn 16
#define DDn 16
#define DHn 32
#define DWn 32
#define Pn  (DDn*DHn*DWn)      /* 16384 */
#define Gn 8
#define K3n 27
#define CGn 16                 /* CS/G */
#define NOFF (K3n*3*Gn)        /* 648 */
#define NTAP (Gn*K3n)          /* 216 */

typedef unsigned long long ull;

// ---------------- f32x2 helpers (FFMA2 — ptxas never emits from C++) -------
__device__ __forceinline__ ull ffma2(ull a, ull b, ull c) {
    ull d;
    asm("fma.rn.f32x2 %0, %1, %2, %3;" : "=l"(d) : "l"(a), "l"(b), "l"(c));
    return d;
}
__device__ __forceinline__ ull dup2(float s) {
    ull d;
    unsigned u = __float_as_uint(s);
    asm("mov.b64 %0, {%1, %1};" : "=l"(d) : "r"(u));
    return d;
}
__device__ __forceinline__ float lo32(ull v) {
    return __uint_as_float((unsigned)(v & 0xffffffffull));
}
__device__ __forceinline__ float hi32(ull v) {
    return __uint_as_float((unsigned)(v >> 32));
}

// -------- device scratch (allocation-free rule: __device__ globals) --------
__device__ float g_src_cl[Bn*SDn*SHn*SWn*CSn];   // [b][z][y][x][c]
__device__ float g_up_cl[Bn*Pn*CSn];             // [b][p][c]
__device__ float g_off[Bn*NOFF*Pn];              // [b][o][p]
__device__ float g_wofft[256*NOFF];              // [c][o]
__device__ float g_ws[NTAP*CGn*CDn];             // [(g*27+k)*16+cg][o]

// -------- prep transposes --------
__global__ void k_transpose_src(const float* __restrict__ src) {
    int i = blockIdx.x * blockDim.x + threadIdx.x;
    const int N = Bn*SDn*SHn*SWn*CSn;
    if (i >= N) return;
    int c = i % CSn;
    int s = (i / CSn) % (SDn*SHn*SWn);
    int b = i / (CSn*SDn*SHn*SWn);
    g_src_cl[i] = src[(b*CSn + c)*(SDn*SHn*SWn) + s];
}

__global__ void k_transpose_woff(const float* __restrict__ w) { // w:[648][256]
    int i = blockIdx.x * blockDim.x + threadIdx.x;
    if (i >= 256*NOFF) return;
    int o = i % NOFF;
    int c = i / NOFF;
    g_wofft[i] = w[o*256 + c];
}

__global__ void k_transpose_wdcn(const float* __restrict__ w) { // w:[o][c][27]
    int i = blockIdx.x * blockDim.x + threadIdx.x;
    if (i >= NTAP*CGn*CDn) return;
    int o  = i % CDn;
    int cg = (i / CDn) % CGn;
    int k  = (i / (CDn*CGn)) % K3n;
    int g  = i / (CDn*CGn*K3n);
    g_ws[i] = w[(o*CSn + g*CGn + cg)*K3n + k];
}

// -------- trilinear 2x upsample (half-pixel, edge-clamped == jax resize) ----
__global__ void k_upsample() {
    int bp = blockIdx.x;                 // Bn*Pn blocks
    int b = bp / Pn;
    int p = bp % Pn;
    int d = p >> 10, h = (p >> 5) & 31, w = p & 31;

    float zc = d*0.5f - 0.25f, yc = h*0.5f - 0.25f, xc = w*0.5f - 0.25f;
    int zf = (int)floorf(zc), yf = (int)floorf(yc), xf = (int)floorf(xc);
    float fz = zc - zf, fy = yc - yf, fx = xc - xf;
    int z0 = min(max(zf,     0), SDn-1), z1 = min(max(zf + 1, 0), SDn-1);
    int y0 = min(max(yf,     0), SHn-1), y1 = min(max(yf + 1, 0), SHn-1);
    int x0 = min(max(xf,     0), SWn-1), x1 = min(max(xf + 1, 0), SWn-1);

    const float* base = g_src_cl + (size_t)b * (SDn*SHn*SWn) * CSn;
    int c = threadIdx.x;  // 128

    float v000 = base[(z0*256 + y0*16 + x0)*CSn + c];
    float v001 = base[(z0*256 + y0*16 + x1)*CSn + c];
    float v010 = base[(z0*256 + y1*16 + x0)*CSn + c];
    float v011 = base[(z0*256 + y1*16 + x1)*CSn + c];
    float v100 = base[(z1*256 + y0*16 + x0)*CSn + c];
    float v101 = base[(z1*256 + y0*16 + x1)*CSn + c];
    float v110 = base[(z1*256 + y1*16 + x0)*CSn + c];
    float v111 = base[(z1*256 + y1*16 + x1)*CSn + c];

    float r0 = (1.f-fy)*((1.f-fx)*v000 + fx*v001) + fy*((1.f-fx)*v010 + fx*v011);
    float r1 = (1.f-fy)*((1.f-fx)*v100 + fx*v101) + fy*((1.f-fx)*v110 + fx*v111);
    g_up_cl[((size_t)b*Pn + p)*CSn + c] = (1.f-fz)*r0 + fz*r1;
}

// -------- 1x1 offset conv (R2 version) --------------------------------------
__global__ void __launch_bounds__(256) k_offset(const float* __restrict__ dst) {
    __shared__ __align__(16) float cat_s[256*32];     // [c][v] 32KB
    int blk = blockIdx.x;               // Bn*(Pn/32)
    int b  = blk / (Pn/32);
    int p0 = (blk % (Pn/32)) * 32;
    int t = threadIdx.x;

    for (int i = t; i < 128*32; i += 256) {
        int c = i >> 5, v = i & 31;
        cat_s[i] = dst[((size_t)b*CDn + c)*Pn + p0 + v];
    }
    for (int i = t; i < 32*128; i += 256) {
        int v = i >> 7, c = i & 127;
        cat_s[(128 + c)*32 + v] = 2.0f * g_up_cl[((size_t)b*Pn + p0 + v)*CSn + c];
    }
    __syncthreads();

    int og = t >> 3;
    int vg = t & 7;
    int v0 = vg * 4;

    #pragma unroll
    for (int pass = 0; pass < 3; ++pass) {
        int o0 = pass*256 + og*8;
        if (o0 >= NOFF) break;
        ull a[4][4];
        #pragma unroll
        for (int i = 0; i < 4; ++i)
            #pragma unroll
            for (int j = 0; j < 4; ++j) a[i][j] = 0ull;

        #pragma unroll 4
        for (int c = 0; c < 256; ++c) {
            const ulonglong2* wrow = (const ulonglong2*)&g_wofft[c*NOFF + o0];
            ulonglong2 wA = wrow[0];
            ulonglong2 wB = wrow[1];
            float4 sv = *(const float4*)&cat_s[c*32 + v0];
            ull s0 = dup2(sv.x), s1 = dup2(sv.y);
            ull s2 = dup2(sv.z), s3 = dup2(sv.w);
            a[0][0] = ffma2(wA.x, s0, a[0][0]); a[0][1] = ffma2(wA.x, s1, a[0][1]);
            a[0][2] = ffma2(wA.x, s2, a[0][2]); a[0][3] = ffma2(wA.x, s3, a[0][3]);
            a[1][0] = ffma2(wA.y, s0, a[1][0]); a[1][1] = ffma2(wA.y, s1, a[1][1]);
            a[1][2] = ffma2(wA.y, s2, a[1][2]); a[1][3] = ffma2(wA.y, s3, a[1][3]);
            a[2][0] = ffma2(wB.x, s0, a[2][0]); a[2][1] = ffma2(wB.x, s1, a[2][1]);
            a[2][2] = ffma2(wB.x, s2, a[2][2]); a[2][3] = ffma2(wB.x, s3, a[2][3]);
            a[3][0] = ffma2(wB.y, s0, a[3][0]); a[3][1] = ffma2(wB.y, s1, a[3][1]);
            a[3][2] = ffma2(wB.y, s2, a[3][2]); a[3][3] = ffma2(wB.y, s3, a[3][3]);
        }

        #pragma unroll
        for (int op = 0; op < 4; ++op) {
            float4 flo = make_float4(lo32(a[op][0]), lo32(a[op][1]),
                                     lo32(a[op][2]), lo32(a[op][3]));
            float4 fhi = make_float4(hi32(a[op][0]), hi32(a[op][1]),
                                     hi32(a[op][2]), hi32(a[op][3]));
            size_t base = ((size_t)b*NOFF + o0 + op*2)*Pn + p0 + v0;
            *(float4*)&g_off[base]              = flo;
            *(float4*)&g_off[base + (size_t)Pn] = fhi;
        }
    }
}

// -------- fused deformable sampling + output GEMM + ReLU (FFMA2) -----------
// block: 128 voxels, 256 threads, double-buffered tiles, 1 sync per tap.
// sampling map: (vv = t>>1, q = t&1) -> channels q*8..q*8+7 of group g
// gemm map:     (og = t>>4 -> 8 o, vg = t&15 -> 8 v = 4 packed v-pairs)
__global__ void __launch_bounds__(256, 2) k_dcn(float* __restrict__ out) {
    __shared__ __align__(16) float  s_tile[2][CGn][128];   // 16KB
    __shared__ __align__(16) float2 wd[2][CGn][CDn];       // 32KB (dup weights)

    int blk = blockIdx.x;               // Bn*(Pn/128) = 256
    int b  = blk >> 7;
    int p0 = (blk & 127) * 128;
    int t  = threadIdx.x;
    int vv = t >> 1, q = t & 1;
    int og = t >> 4, vg = t & 15;
    int o0 = og * 8, v0 = vg * 8;

    int p = p0 + vv;
    int d = p >> 10, h = (p >> 5) & 31, w = p & 31;

    ull acc[8][4];                      // 8 o x 4 v-pairs
    #pragma unroll
    for (int o = 0; o < 8; ++o)
        #pragma unroll
        for (int j = 0; j < 4; ++j) acc[o][j] = 0ull;

    const size_t offB = (size_t)b * NOFF * Pn;
    const float* upB  = g_up_cl + (size_t)b*Pn*CSn;

    // ---- sampling (8 channels) + weight staging for tap kk into buf ----
    auto sample = [&](int kk, int buf) {
        int g = kk / K3n, k = kk % K3n;
        int kz = k/9 - 1, ky = (k/3)%3 - 1, kx = k%3 - 1;
        int ob = (g*K3n + k)*3;
        float z = d + kz + g_off[offB + (size_t)(ob+0)*Pn + p];
        float y = h + ky + g_off[offB + (size_t)(ob+1)*Pn + p];
        float x = w + kx + g_off[offB + (size_t)(ob+2)*Pn + p];

        float z0f = floorf(z), y0f = floorf(y), x0f = floorf(x);
        float fz = z - z0f, fy = y - y0f, fx = x - x0f;
        int z0 = (int)z0f, y0 = (int)y0f, x0 = (int)x0f;

        const float* upg = upB + g*CGn + q*8;
        ull sa[4] = {0ull, 0ull, 0ull, 0ull};   // 8 channels as 4 f32x2
        #pragma unroll
        for (int cnr = 0; cnr < 8; ++cnr) {
            int dz = cnr>>2, dy = (cnr>>1)&1, dx = cnr&1;
            int iz = z0+dz, iy = y0+dy, ix = x0+dx;
            float wt = (dz ? fz : 1.f-fz) * (dy ? fy : 1.f-fy) * (dx ? fx : 1.f-fx);
            bool ok = (iz>=0) & (iz<DDn) & (iy>=0) & (iy<DHn) & (ix>=0) & (ix<DWn);
            wt = ok ? wt : 0.f;
            int ci = min(max(iz,0),DDn-1)*1024 + min(max(iy,0),DHn-1)*32 + min(max(ix,0),DWn-1);
            const ulonglong2* vp = (const ulonglong2*)(upg + (size_t)ci*CSn);
            ulonglong2 va = vp[0], vb = vp[1];
            ull wdp = dup2(wt);
            sa[0] = ffma2(va.x, wdp, sa[0]); sa[1] = ffma2(va.y, wdp, sa[1]);
            sa[2] = ffma2(vb.x, wdp, sa[2]); sa[3] = ffma2(vb.y, wdp, sa[3]);
        }
        #pragma unroll
        for (int j = 0; j < 4; ++j) {
            s_tile[buf][q*8 + 2*j    ][vv] = lo32(sa[j]);
            s_tile[buf][q*8 + 2*j + 1][vv] = hi32(sa[j]);
        }

        // stage duplicated weight slice [16][128] -> wd (float4 vectorized)
        const float4* wsrc = (const float4*)&g_ws[kk*(CGn*CDn)];
        float4 wa = wsrc[t*2], wb = wsrc[t*2+1];
        float4* wdst = (float4*)&wd[buf][0][0] + t*4;
        wdst[0] = make_float4(wa.x, wa.x, wa.y, wa.y);
        wdst[1] = make_float4(wa.z, wa.z, wa.w, wa.w);
        wdst[2] = make_float4(wb.x, wb.x, wb.y, wb.y);
        wdst[3] = make_float4(wb.z, wb.z, wb.w, wb.w);
    };

    sample(0, 0);
    __syncthreads();

    for (int kk = 0; kk < NTAP; ++kk) {
        int cur = kk & 1;

        #pragma unroll
        for (int cg = 0; cg < CGn; ++cg) {
            ulonglong2 sA = *(const ulonglong2*)&s_tile[cur][cg][v0];
            ulonglong2 sB = *(const ulonglong2*)&s_tile[cur][cg][v0+4];
            const ulonglong2* wr = (const ulonglong2*)&wd[cur][cg][o0]; // bcast
            ulonglong2 w01 = wr[0], w23 = wr[1], w45 = wr[2], w67 = wr[3];
            acc[0][0]=ffma2(w01.x,sA.x,acc[0][0]); acc[0][1]=ffma2(w01.x,sA.y,acc[0][1]);
            acc[0][2]=ffma2(w01.x,sB.x,acc[0][2]); acc[0][3]=ffma2(w01.x,sB.y,acc[0][3]);
            acc[1][0]=ffma2(w01.y,sA.x,acc[1][0]); acc[1][1]=ffma2(w01.y,sA.y,acc[1][1]);
            acc[1][2]=ffma2(w01.y,sB.x,acc[1][2]); acc[1][3]=ffma2(w01.y,sB.y,acc[1][3]);
            acc[2][0]=ffma2(w23.x,sA.x,acc[2][0]); acc[2][1]=ffma2(w23.x,sA.y,acc[2][1]);
            acc[2][2]=ffma2(w23.x,sB.x,acc[2][2]); acc[2][3]=ffma2(w23.x,sB.y,acc[2][3]);
            acc[3][0]=ffma2(w23.y,sA.x,acc[3][0]); acc[3][1]=ffma2(w23.y,sA.y,acc[3][1]);
            acc[3][2]=ffma2(w23.y,sB.x,acc[3][2]); acc[3][3]=ffma2(w23.y,sB.y,acc[3][3]);
            acc[4][0]=ffma2(w45.x,sA.x,acc[4][0]); acc[4][1]=ffma2(w45.x,sA.y,acc[4][1]);
            acc[4][2]=ffma2(w45.x,sB.x,acc[4][2]); acc[4][3]=ffma2(w45.x,sB.y,acc[4][3]);
            acc[5][0]=ffma2(w45.y,sA.x,acc[5][0]); acc[5][1]=ffma2(w45.y,sA.y,acc[5][1]);
            acc[5][2]=ffma2(w45.y,sB.x,acc[5][2]); acc[5][3]=ffma2(w45.y,sB.y,acc[5][3]);
            acc[6][0]=ffma2(w67.x,sA.x,acc[6][0]); acc[6][1]=ffma2(w67.x,sA.y,acc[6][1]);
            acc[6][2]=ffma2(w67.x,sB.x,acc[6][2]); acc[6][3]=ffma2(w67.x,sB.y,acc[6][3]);
            acc[7][0]=ffma2(w67.y,sA.x,acc[7][0]); acc[7][1]=ffma2(w67.y,sA.y,acc[7][1]);
            acc[7][2]=ffma2(w67.y,sB.x,acc[7][2]); acc[7][3]=ffma2(w67.y,sB.y,acc[7][3]);
        }

        if (kk + 1 < NTAP) sample(kk + 1, cur ^ 1);
        __syncthreads();
    }

    // ReLU + write out[b][o0+o][p0+v0 .. +7]
    #pragma unroll
    for (int o = 0; o < 8; ++o) {
        float4 f0 = make_float4(fmaxf(lo32(acc[o][0]),0.f), fmaxf(hi32(acc[o][0]),0.f),
                                fmaxf(lo32(acc[o][1]),0.f), fmaxf(hi32(acc[o][1]),0.f));
        float4 f1 = make_float4(fmaxf(lo32(acc[o][2]),0.f), fmaxf(hi32(acc[o][2]),0.f),
                                fmaxf(lo32(acc[o][3]),0.f), fmaxf(hi32(acc[o][3]),0.f));
        size_t base = ((size_t)b*CDn + o0 + o)*Pn + p0 + v0;
        *(float4*)&out[base]     = f0;
        *(float4*)&out[base + 4] = f1;
    }
}

extern "C" void kernel_launch(void* const* d_in, const int* in_sizes, int n_in,
                              void* d_out, int out_size) {
    const float* src  = (const float*)d_in[0];   // feat_1x_src [2,128,8,16,16]
    const float* dst  = (const float*)d_in[1];   // feat_2x_dst [2,128,16,32,32]
    const float* woff = (const float*)d_in[2];   // w_offset [648,256]
    const float* wdcn = (const float*)d_in[3];   // w_dcn [128,128,3,3,3]
    float* out = (float*)d_out;

    k_transpose_src <<<(Bn*SDn*SHn*SWn*CSn + 255)/256, 256>>>(src);
    k_transpose_woff<<<(256*NOFF + 255)/256, 256>>>(woff);
    k_transpose_wdcn<<<(NTAP*CGn*CDn + 255)/256, 256>>>(wdcn);
    k_upsample      <<<Bn*Pn, 128>>>();
    k_offset        <<<Bn*(Pn/32), 256>>>(dst);
    k_dcn           <<<Bn*(Pn/128), 256>>>(out);
}

// round 6
// speedup vs baseline: 1.5456x; 1.4068x over previous
#include <cuda_runtime.h>
#include <cuda_bf16.h>
#include <cstdint>

#define Bn 2
#define CSn 128
#define CDn 128
#define SDn 8
#define SHn 16
#define SWn 16
#define DDn 16
#define DHn 32
#define DWn 32
#define Pn  (DDn*DHn*DWn)      /* 16384 */
#define Gn 8
#define K3n 27
#define CGn 16                 /* CS/G */
#define NOFF (K3n*3*Gn)        /* 648 */
#define NTAP (Gn*K3n)          /* 216 */
#define WROW 80                /* padded row bytes of A/B smem tiles */
#define WTILE (128*WROW)       /* 10240 B per tap tile */

typedef unsigned long long ull;

// ---------------- f32x2 helpers (issue-slot savers) ------------------------
__device__ __forceinline__ ull ffma2(ull a, ull b, ull c) {
    ull d;
    asm("fma.rn.f32x2 %0, %1, %2, %3;" : "=l"(d) : "l"(a), "l"(b), "l"(c));
    return d;
}
__device__ __forceinline__ ull dup2(float s) {
    ull d;
    unsigned u = __float_as_uint(s);
    asm("mov.b64 %0, {%1, %1};" : "=l"(d) : "r"(u));
    return d;
}
__device__ __forceinline__ float lo32(ull v) {
    return __uint_as_float((unsigned)(v & 0xffffffffull));
}
__device__ __forceinline__ float hi32(ull v) {
    return __uint_as_float((unsigned)(v >> 32));
}

// ---------------- tensor-core helpers ---------------------------------------
__device__ __forceinline__ void ldsm4(uint32_t* r, uint32_t addr) {
    asm volatile("ldmatrix.sync.aligned.m8n8.x4.shared.b16 {%0,%1,%2,%3},[%4];"
        : "=r"(r[0]), "=r"(r[1]), "=r"(r[2]), "=r"(r[3]) : "r"(addr));
}
__device__ __forceinline__ void mma16816(float* d, const uint32_t* a,
                                         uint32_t b0, uint32_t b1) {
    asm volatile(
        "mma.sync.aligned.m16n8k16.row.col.f32.bf16.bf16.f32 "
        "{%0,%1,%2,%3},{%4,%5,%6,%7},{%8,%9},{%0,%1,%2,%3};"
        : "+f"(d[0]), "+f"(d[1]), "+f"(d[2]), "+f"(d[3])
        : "r"(a[0]), "r"(a[1]), "r"(a[2]), "r"(a[3]), "r"(b0), "r"(b1));
}
__device__ __forceinline__ uint32_t packbf(__nv_bfloat16 a, __nv_bfloat16 b) {
    __nv_bfloat162 t = __halves2bfloat162(a, b);
    return *(uint32_t*)&t;
}

// -------- device scratch ----------------------------------------------------
__device__ float g_src_cl[Bn*SDn*SHn*SWn*CSn];   // [b][z][y][x][c]
__device__ float g_up_cl[Bn*Pn*CSn];             // [b][p][c]
__device__ float g_off[Bn*NOFF*Pn];              // [b][o][p]
__device__ float g_wofft[256*NOFF];              // [c][o]
__device__ __align__(16) uint8_t g_wsplit[(size_t)NTAP*WTILE]; // bf16 hi/lo image

// -------- prep: all transposes + bf16 weight split --------------------------
__global__ void k_prep(const float* __restrict__ src,
                       const float* __restrict__ woff,
                       const float* __restrict__ wdcn) {
    int i = blockIdx.x * blockDim.x + threadIdx.x;
    const int N1 = Bn*SDn*SHn*SWn*CSn;    // 524288
    const int N2 = 256*NOFF;              // 165888
    const int N3 = NTAP*128*CGn;          // 442368
    if (i < N1) {
        int c = i % CSn;
        int s = (i / CSn) % (SDn*SHn*SWn);
        int b = i / (CSn*SDn*SHn*SWn);
        g_src_cl[i] = src[(b*CSn + c)*(SDn*SHn*SWn) + s];
    } else if (i < N1 + N2) {
        int j = i - N1;
        int o = j % NOFF;
        int c = j / NOFF;
        g_wofft[j] = woff[o*256 + c];
    } else if (i < N1 + N2 + N3) {
        int j = i - N1 - N2;
        int cg = j % CGn;
        int o  = (j / CGn) % 128;
        int kk = j / (CGn*128);
        int g = kk / K3n, k = kk % K3n;
        float wv = wdcn[((o*CSn) + g*CGn + cg)*K3n + k];
        __nv_bfloat16 hb = __float2bfloat16(wv);
        __nv_bfloat16 lb = __float2bfloat16(wv - __bfloat162float(hb));
        uint8_t* row = g_wsplit + (size_t)kk*WTILE + o*WROW;
        *(__nv_bfloat16*)(row + cg*2)      = hb;
        *(__nv_bfloat16*)(row + 32 + cg*2) = lb;
    }
}

// -------- trilinear 2x upsample ----------------------------------------------
__global__ void k_upsample() {
    int bp = blockIdx.x;                 // Bn*Pn blocks
    int b = bp / Pn;
    int p = bp % Pn;
    int d = p >> 10, h = (p >> 5) & 31, w = p & 31;

    float zc = d*0.5f - 0.25f, yc = h*0.5f - 0.25f, xc = w*0.5f - 0.25f;
    int zf = (int)floorf(zc), yf = (int)floorf(yc), xf = (int)floorf(xc);
    float fz = zc - zf, fy = yc - yf, fx = xc - xf;
    int z0 = min(max(zf,     0), SDn-1), z1 = min(max(zf + 1, 0), SDn-1);
    int y0 = min(max(yf,     0), SHn-1), y1 = min(max(yf + 1, 0), SHn-1);
    int x0 = min(max(xf,     0), SWn-1), x1 = min(max(xf + 1, 0), SWn-1);

    const float* base = g_src_cl + (size_t)b * (SDn*SHn*SWn) * CSn;
    int c = threadIdx.x;  // 128

    float v000 = base[(z0*256 + y0*16 + x0)*CSn + c];
    float v001 = base[(z0*256 + y0*16 + x1)*CSn + c];
    float v010 = base[(z0*256 + y1*16 + x0)*CSn + c];
    float v011 = base[(z0*256 + y1*16 + x1)*CSn + c];
    float v100 = base[(z1*256 + y0*16 + x0)*CSn + c];
    float v101 = base[(z1*256 + y0*16 + x1)*CSn + c];
    float v110 = base[(z1*256 + y1*16 + x0)*CSn + c];
    float v111 = base[(z1*256 + y1*16 + x1)*CSn + c];

    float r0 = (1.f-fy)*((1.f-fx)*v000 + fx*v001) + fy*((1.f-fx)*v010 + fx*v011);
    float r1 = (1.f-fy)*((1.f-fx)*v100 + fx*v101) + fy*((1.f-fx)*v110 + fx*v111);
    g_up_cl[((size_t)b*Pn + p)*CSn + c] = (1.f-fz)*r0 + fz*r1;
}

// -------- 1x1 offset conv (FFMA2, unchanged) ---------------------------------
__global__ void __launch_bounds__(256) k_offset(const float* __restrict__ dst) {
    __shared__ __align__(16) float cat_s[256*32];     // [c][v] 32KB
    int blk = blockIdx.x;               // Bn*(Pn/32)
    int b  = blk / (Pn/32);
    int p0 = (blk % (Pn/32)) * 32;
    int t = threadIdx.x;

    for (int i = t; i < 128*32; i += 256) {
        int c = i >> 5, v = i & 31;
        cat_s[i] = dst[((size_t)b*CDn + c)*Pn + p0 + v];
    }
    for (int i = t; i < 32*128; i += 256) {
        int v = i >> 7, c = i & 127;
        cat_s[(128 + c)*32 + v] = 2.0f * g_up_cl[((size_t)b*Pn + p0 + v)*CSn + c];
    }
    __syncthreads();

    int og = t >> 3;
    int vg = t & 7;
    int v0 = vg * 4;

    #pragma unroll
    for (int pass = 0; pass < 3; ++pass) {
        int o0 = pass*256 + og*8;
        if (o0 >= NOFF) break;
        ull a[4][4];
        #pragma unroll
        for (int i = 0; i < 4; ++i)
            #pragma unroll
            for (int j = 0; j < 4; ++j) a[i][j] = 0ull;

        #pragma unroll 4
        for (int c = 0; c < 256; ++c) {
            const ulonglong2* wrow = (const ulonglong2*)&g_wofft[c*NOFF + o0];
            ulonglong2 wA = wrow[0];
            ulonglong2 wB = wrow[1];
            float4 sv = *(const float4*)&cat_s[c*32 + v0];
            ull s0 = dup2(sv.x), s1 = dup2(sv.y);
            ull s2 = dup2(sv.z), s3 = dup2(sv.w);
            a[0][0] = ffma2(wA.x, s0, a[0][0]); a[0][1] = ffma2(wA.x, s1, a[0][1]);
            a[0][2] = ffma2(wA.x, s2, a[0][2]); a[0][3] = ffma2(wA.x, s3, a[0][3]);
            a[1][0] = ffma2(wA.y, s0, a[1][0]); a[1][1] = ffma2(wA.y, s1, a[1][1]);
            a[1][2] = ffma2(wA.y, s2, a[1][2]); a[1][3] = ffma2(wA.y, s3, a[1][3]);
            a[2][0] = ffma2(wB.x, s0, a[2][0]); a[2][1] = ffma2(wB.x, s1, a[2][1]);
            a[2][2] = ffma2(wB.x, s2, a[2][2]); a[2][3] = ffma2(wB.x, s3, a[2][3]);
            a[3][0] = ffma2(wB.y, s0, a[3][0]); a[3][1] = ffma2(wB.y, s1, a[3][1]);
            a[3][2] = ffma2(wB.y, s2, a[3][2]); a[3][3] = ffma2(wB.y, s3, a[3][3]);
        }

        #pragma unroll
        for (int op = 0; op < 4; ++op) {
            float4 flo = make_float4(lo32(a[op][0]), lo32(a[op][1]),
                                     lo32(a[op][2]), lo32(a[op][3]));
            float4 fhi = make_float4(hi32(a[op][0]), hi32(a[op][1]),
                                     hi32(a[op][2]), hi32(a[op][3]));
            size_t base = ((size_t)b*NOFF + o0 + op*2)*Pn + p0 + v0;
            *(float4*)&g_off[base]              = flo;
            *(float4*)&g_off[base + (size_t)Pn] = fhi;
        }
    }
}

// -------- fused deformable sampling + bf16-split tensor GEMM + ReLU ---------
// block: 128 voxels, 256 threads.
// sampling: (vv = t>>2 [+64 per pass], q = t&3) -> 4 channels of group g
// mma: warp w owns o rows 16w..16w+15; D output-stationary (64 fp32 regs).
__global__ void __launch_bounds__(256, 1) k_dcn(float* __restrict__ out) {
    __shared__ __align__(16) uint8_t sW[2][WTILE];   // A tiles (hi|lo), 20KB
    __shared__ __align__(16) uint8_t sS[2][WTILE];   // B tiles (hi|lo), 20KB

    int blk = blockIdx.x;               // Bn*(Pn/128) = 256
    int b  = blk >> 7;
    int p0 = (blk & 127) * 128;
    int t  = threadIdx.x;
    int w  = t >> 5, l = t & 31;
    int vvb = t >> 2, q = t & 3;

    float dacc[16][4];
    #pragma unroll
    for (int n = 0; n < 16; ++n)
        #pragma unroll
        for (int j = 0; j < 4; ++j) dacc[n][j] = 0.f;

    const size_t offB = (size_t)b * NOFF * Pn;
    const float* upB  = g_up_cl + (size_t)b*Pn*CSn;

    // ---- sampling (2 passes of 64 voxels) + W staging for tap kk -> buf ----
    auto sample = [&](int kk, int buf) {
        int g = kk / K3n, k = kk % K3n;
        int kz = k/9 - 1, ky = (k/3)%3 - 1, kx = k%3 - 1;
        int ob = (g*K3n + k)*3;
        const float* upg = upB + g*CGn + q*4;

        #pragma unroll
        for (int ph = 0; ph < 2; ++ph) {
            int vv = vvb + ph*64;
            int p = p0 + vv;
            int d = p >> 10, h = (p >> 5) & 31, wx = p & 31;

            float z = d  + kz + g_off[offB + (size_t)(ob+0)*Pn + p];
            float y = h  + ky + g_off[offB + (size_t)(ob+1)*Pn + p];
            float x = wx + kx + g_off[offB + (size_t)(ob+2)*Pn + p];

            float z0f = floorf(z), y0f = floorf(y), x0f = floorf(x);
            float fz = z - z0f, fy = y - y0f, fx = x - x0f;
            int z0 = (int)z0f, y0 = (int)y0f, x0 = (int)x0f;

            float4 sa = make_float4(0.f, 0.f, 0.f, 0.f);
            #pragma unroll
            for (int cnr = 0; cnr < 8; ++cnr) {
                int dz = cnr>>2, dy = (cnr>>1)&1, dx = cnr&1;
                int iz = z0+dz, iy = y0+dy, ix = x0+dx;
                float wt = (dz ? fz : 1.f-fz) * (dy ? fy : 1.f-fy) * (dx ? fx : 1.f-fx);
                bool ok = (iz>=0) & (iz<DDn) & (iy>=0) & (iy<DHn) & (ix>=0) & (ix<DWn);
                wt = ok ? wt : 0.f;
                int ci = min(max(iz,0),DDn-1)*1024 + min(max(iy,0),DHn-1)*32 + min(max(ix,0),DWn-1);
                float4 v = *(const float4*)(upg + (size_t)ci*CSn);
                sa.x += wt*v.x; sa.y += wt*v.y; sa.z += wt*v.z; sa.w += wt*v.w;
            }
            // bf16 split: hi + lo
            __nv_bfloat16 h0 = __float2bfloat16(sa.x);
            __nv_bfloat16 h1 = __float2bfloat16(sa.y);
            __nv_bfloat16 h2 = __float2bfloat16(sa.z);
            __nv_bfloat16 h3 = __float2bfloat16(sa.w);
            __nv_bfloat16 l0 = __float2bfloat16(sa.x - __bfloat162float(h0));
            __nv_bfloat16 l1 = __float2bfloat16(sa.y - __bfloat162float(h1));
            __nv_bfloat16 l2 = __float2bfloat16(sa.z - __bfloat162float(h2));
            __nv_bfloat16 l3 = __float2bfloat16(sa.w - __bfloat162float(h3));
            uint8_t* rowp = sS[buf] + vv*WROW + q*8;
            *(uint2*)rowp        = make_uint2(packbf(h0,h1), packbf(h2,h3));
            *(uint2*)(rowp + 32) = make_uint2(packbf(l0,l1), packbf(l2,l3));
        }

        // stage pre-split W tile (10240 B) for this tap
        const uint4* srcW = (const uint4*)(g_wsplit + (size_t)kk*WTILE);
        uint4* dstW = (uint4*)sW[buf];
        #pragma unroll
        for (int i = t; i < WTILE/16; i += 256) dstW[i] = srcW[i];
    };

    // ---- tensor GEMM on buffer buf ----
    auto domma = [&](int buf) {
        uint32_t sWb = (uint32_t)__cvta_generic_to_shared(&sW[buf][0]);
        uint32_t sSb = (uint32_t)__cvta_generic_to_shared(&sS[buf][0]);
        uint32_t aaddr = sWb + (w*16 + (l & 15))*WROW + (l >> 4)*16;
        uint32_t ah[4], al[4];
        ldsm4(ah, aaddr);
        ldsm4(al, aaddr + 32);
        uint32_t brow = 8*(l >> 4) + (l & 7);
        uint32_t bcol = ((l >> 3) & 1)*16;
        #pragma unroll
        for (int nc = 0; nc < 8; ++nc) {
            uint32_t baddr = sSb + (nc*16 + brow)*WROW + bcol;
            uint32_t bh[4], bl[4];
            ldsm4(bh, baddr);        // non-trans: sS is [n][k], matches B frag
            ldsm4(bl, baddr + 32);
            // D += Wh*Sh + Wh*Sl + Wl*Sh   (fp32 accumulate)
            mma16816(dacc[2*nc  ], ah, bh[0], bh[1]);
            mma16816(dacc[2*nc  ], ah, bl[0], bl[1]);
            mma16816(dacc[2*nc  ], al, bh[0], bh[1]);
            mma16816(dacc[2*nc+1], ah, bh[2], bh[3]);
            mma16816(dacc[2*nc+1], ah, bl[2], bl[3]);
            mma16816(dacc[2*nc+1], al, bh[2], bh[3]);
        }
    };

    sample(0, 0);
    __syncthreads();

    for (int kk = 0; kk < NTAP; ++kk) {
        int cur = kk & 1;
        domma(cur);
        if (kk + 1 < NTAP) sample(kk + 1, cur ^ 1);
        __syncthreads();
    }

    // ---- epilogue: ReLU + STG.64 ----
    int g = l >> 2, tq = l & 3;
    size_t base0 = ((size_t)b*CDn + w*16 + g)*Pn + p0 + 2*tq;
    size_t base1 = base0 + (size_t)8*Pn;
    #pragma unroll
    for (int n = 0; n < 16; ++n) {
        float2 v0 = make_float2(fmaxf(dacc[n][0], 0.f), fmaxf(dacc[n][1], 0.f));
        float2 v1 = make_float2(fmaxf(dacc[n][2], 0.f), fmaxf(dacc[n][3], 0.f));
        *(float2*)&out[base0 + n*8] = v0;
        *(float2*)&out[base1 + n*8] = v1;
    }
}

extern "C" void kernel_launch(void* const* d_in, const int* in_sizes, int n_in,
                              void* d_out, int out_size) {
    const float* src  = (const float*)d_in[0];   // feat_1x_src [2,128,8,16,16]
    const float* dst  = (const float*)d_in[1];   // feat_2x_dst [2,128,16,32,32]
    const float* woff = (const float*)d_in[2];   // w_offset [648,256]
    const float* wdcn = (const float*)d_in[3];   // w_dcn [128,128,3,3,3]
    float* out = (float*)d_out;

    const int NPREP = Bn*SDn*SHn*SWn*CSn + 256*NOFF + NTAP*128*CGn;
    k_prep     <<<(NPREP + 255)/256, 256>>>(src, woff, wdcn);
    k_upsample <<<Bn*Pn, 128>>>();
    k_offset   <<<Bn*(Pn/32), 256>>>(dst);
    k_dcn      <<<Bn*(Pn/128), 256>>>(out);
}

// round 7
// speedup vs baseline: 1.6468x; 1.0655x over previous
#include <cuda_runtime.h>
#include <cuda_bf16.h>
#include <cstdint>

#define Bn 2
#define CSn 128
#define CDn 128
#define SDn 8
#define SHn 16
#define SWn 16
#define DDn 16
#define DHn 32
#define DWn 32
#define Pn  (DDn*DHn*DWn)      /* 16384 */
#define Gn 8
#define K3n 27
#define CGn 16                 /* CS/G */
#define NOFF (K3n*3*Gn)        /* 648 */
#define NTAP (Gn*K3n)          /* 216 */
#define WROW 80                /* padded row bytes of A/B smem tiles */
#define WTILE (128*WROW)       /* 10240 B per tap tile */

typedef unsigned long long ull;

// ---------------- f32x2 helpers (issue-slot savers) ------------------------
__device__ __forceinline__ ull ffma2(ull a, ull b, ull c) {
    ull d;
    asm("fma.rn.f32x2 %0, %1, %2, %3;" : "=l"(d) : "l"(a), "l"(b), "l"(c));
    return d;
}
__device__ __forceinline__ ull dup2(float s) {
    ull d;
    unsigned u = __float_as_uint(s);
    asm("mov.b64 %0, {%1, %1};" : "=l"(d) : "r"(u));
    return d;
}
__device__ __forceinline__ float lo32(ull v) {
    return __uint_as_float((unsigned)(v & 0xffffffffull));
}
__device__ __forceinline__ float hi32(ull v) {
    return __uint_as_float((unsigned)(v >> 32));
}

// ---------------- tensor-core helpers ---------------------------------------
__device__ __forceinline__ void ldsm4(uint32_t* r, uint32_t addr) {
    asm volatile("ldmatrix.sync.aligned.m8n8.x4.shared.b16 {%0,%1,%2,%3},[%4];"
        : "=r"(r[0]), "=r"(r[1]), "=r"(r[2]), "=r"(r[3]) : "r"(addr));
}
__device__ __forceinline__ void mma16816(float* d, const uint32_t* a,
                                         uint32_t b0, uint32_t b1) {
    asm volatile(
        "mma.sync.aligned.m16n8k16.row.col.f32.bf16.bf16.f32 "
        "{%0,%1,%2,%3},{%4,%5,%6,%7},{%8,%9},{%0,%1,%2,%3};"
        : "+f"(d[0]), "+f"(d[1]), "+f"(d[2]), "+f"(d[3])
        : "r"(a[0]), "r"(a[1]), "r"(a[2]), "r"(a[3]), "r"(b0), "r"(b1));
}
__device__ __forceinline__ uint32_t packbf(__nv_bfloat16 a, __nv_bfloat16 b) {
    __nv_bfloat162 t = __halves2bfloat162(a, b);
    return *(uint32_t*)&t;
}

// -------- device scratch ----------------------------------------------------
__device__ float g_src_cl[Bn*SDn*SHn*SWn*CSn];   // [b][z][y][x][c]
__device__ float g_up_cl[Bn*Pn*CSn];             // [b][p][c]
__device__ float g_off[Bn*NOFF*Pn];              // [b][o][p]
__device__ float g_wofft[256*NOFF];              // [c][o]
__device__ __align__(16) uint8_t g_wsplit[(size_t)NTAP*WTILE]; // bf16 hi/lo image

// -------- prep: all transposes + bf16 weight split --------------------------
__global__ void k_prep(const float* __restrict__ src,
                       const float* __restrict__ woff,
                       const float* __restrict__ wdcn) {
    int i = blockIdx.x * blockDim.x + threadIdx.x;
    const int N1 = Bn*SDn*SHn*SWn*CSn;    // 524288
    const int N2 = 256*NOFF;              // 165888
    const int N3 = NTAP*128*CGn;          // 442368
    if (i < N1) {
        int c = i % CSn;
        int s = (i / CSn) % (SDn*SHn*SWn);
        int b = i / (CSn*SDn*SHn*SWn);
        g_src_cl[i] = src[(b*CSn + c)*(SDn*SHn*SWn) + s];
    } else if (i < N1 + N2) {
        int j = i - N1;
        int o = j % NOFF;
        int c = j / NOFF;
        g_wofft[j] = woff[o*256 + c];
    } else if (i < N1 + N2 + N3) {
        int j = i - N1 - N2;
        int cg = j % CGn;
        int o  = (j / CGn) % 128;
        int kk = j / (CGn*128);
        int g = kk / K3n, k = kk % K3n;
        float wv = wdcn[((o*CSn) + g*CGn + cg)*K3n + k];
        __nv_bfloat16 hb = __float2bfloat16(wv);
        __nv_bfloat16 lb = __float2bfloat16(wv - __bfloat162float(hb));
        uint8_t* row = g_wsplit + (size_t)kk*WTILE + o*WROW;
        *(__nv_bfloat16*)(row + cg*2)      = hb;
        *(__nv_bfloat16*)(row + 32 + cg*2) = lb;
    }
}

// -------- trilinear 2x upsample ----------------------------------------------
__global__ void k_upsample() {
    int bp = blockIdx.x;                 // Bn*Pn blocks
    int b = bp / Pn;
    int p = bp % Pn;
    int d = p >> 10, h = (p >> 5) & 31, w = p & 31;

    float zc = d*0.5f - 0.25f, yc = h*0.5f - 0.25f, xc = w*0.5f - 0.25f;
    int zf = (int)floorf(zc), yf = (int)floorf(yc), xf = (int)floorf(xc);
    float fz = zc - zf, fy = yc - yf, fx = xc - xf;
    int z0 = min(max(zf,     0), SDn-1), z1 = min(max(zf + 1, 0), SDn-1);
    int y0 = min(max(yf,     0), SHn-1), y1 = min(max(yf + 1, 0), SHn-1);
    int x0 = min(max(xf,     0), SWn-1), x1 = min(max(xf + 1, 0), SWn-1);

    const float* base = g_src_cl + (size_t)b * (SDn*SHn*SWn) * CSn;
    int c = threadIdx.x;  // 128

    float v000 = base[(z0*256 + y0*16 + x0)*CSn + c];
    float v001 = base[(z0*256 + y0*16 + x1)*CSn + c];
    float v010 = base[(z0*256 + y1*16 + x0)*CSn + c];
    float v011 = base[(z0*256 + y1*16 + x1)*CSn + c];
    float v100 = base[(z1*256 + y0*16 + x0)*CSn + c];
    float v101 = base[(z1*256 + y0*16 + x1)*CSn + c];
    float v110 = base[(z1*256 + y1*16 + x0)*CSn + c];
    float v111 = base[(z1*256 + y1*16 + x1)*CSn + c];

    float r0 = (1.f-fy)*((1.f-fx)*v000 + fx*v001) + fy*((1.f-fx)*v010 + fx*v011);
    float r1 = (1.f-fy)*((1.f-fx)*v100 + fx*v101) + fy*((1.f-fx)*v110 + fx*v111);
    g_up_cl[((size_t)b*Pn + p)*CSn + c] = (1.f-fz)*r0 + fz*r1;
}

// -------- 1x1 offset conv (FFMA2, unchanged) ---------------------------------
__global__ void __launch_bounds__(256) k_offset(const float* __restrict__ dst) {
    __shared__ __align__(16) float cat_s[256*32];     // [c][v] 32KB
    int blk = blockIdx.x;               // Bn*(Pn/32)
    int b  = blk / (Pn/32);
    int p0 = (blk % (Pn/32)) * 32;
    int t = threadIdx.x;

    for (int i = t; i < 128*32; i += 256) {
        int c = i >> 5, v = i & 31;
        cat_s[i] = dst[((size_t)b*CDn + c)*Pn + p0 + v];
    }
    for (int i = t; i < 32*128; i += 256) {
        int v = i >> 7, c = i & 127;
        cat_s[(128 + c)*32 + v] = 2.0f * g_up_cl[((size_t)b*Pn + p0 + v)*CSn + c];
    }
    __syncthreads();

    int og = t >> 3;
    int vg = t & 7;
    int v0 = vg * 4;

    #pragma unroll
    for (int pass = 0; pass < 3; ++pass) {
        int o0 = pass*256 + og*8;
        if (o0 >= NOFF) break;
        ull a[4][4];
        #pragma unroll
        for (int i = 0; i < 4; ++i)
            #pragma unroll
            for (int j = 0; j < 4; ++j) a[i][j] = 0ull;

        #pragma unroll 4
        for (int c = 0; c < 256; ++c) {
            const ulonglong2* wrow = (const ulonglong2*)&g_wofft[c*NOFF + o0];
            ulonglong2 wA = wrow[0];
            ulonglong2 wB = wrow[1];
            float4 sv = *(const float4*)&cat_s[c*32 + v0];
            ull s0 = dup2(sv.x), s1 = dup2(sv.y);
            ull s2 = dup2(sv.z), s3 = dup2(sv.w);
            a[0][0] = ffma2(wA.x, s0, a[0][0]); a[0][1] = ffma2(wA.x, s1, a[0][1]);
            a[0][2] = ffma2(wA.x, s2, a[0][2]); a[0][3] = ffma2(wA.x, s3, a[0][3]);
            a[1][0] = ffma2(wA.y, s0, a[1][0]); a[1][1] = ffma2(wA.y, s1, a[1][1]);
            a[1][2] = ffma2(wA.y, s2, a[1][2]); a[1][3] = ffma2(wA.y, s3, a[1][3]);
            a[2][0] = ffma2(wB.x, s0, a[2][0]); a[2][1] = ffma2(wB.x, s1, a[2][1]);
            a[2][2] = ffma2(wB.x, s2, a[2][2]); a[2][3] = ffma2(wB.x, s3, a[2][3]);
            a[3][0] = ffma2(wB.y, s0, a[3][0]); a[3][1] = ffma2(wB.y, s1, a[3][1]);
            a[3][2] = ffma2(wB.y, s2, a[3][2]); a[3][3] = ffma2(wB.y, s3, a[3][3]);
        }

        #pragma unroll
        for (int op = 0; op < 4; ++op) {
            float4 flo = make_float4(lo32(a[op][0]), lo32(a[op][1]),
                                     lo32(a[op][2]), lo32(a[op][3]));
            float4 fhi = make_float4(hi32(a[op][0]), hi32(a[op][1]),
                                     hi32(a[op][2]), hi32(a[op][3]));
            size_t base = ((size_t)b*NOFF + o0 + op*2)*Pn + p0 + v0;
            *(float4*)&g_off[base]              = flo;
            *(float4*)&g_off[base + (size_t)Pn] = fhi;
        }
    }
}

// -------- fused deformable sampling + bf16-split tensor GEMM + ReLU ---------
// block: 128 voxels, 512 threads / 16 warps.
// sampling: (vv = t>>2, q = t&3) -> one voxel, 4 channels of group g
// mma: warp w -> o-strip ow = w>>1 (16 rows), voxel half nh = w&1 (64 voxels)
__global__ void __launch_bounds__(512, 1) k_dcn(float* __restrict__ out) {
    __shared__ __align__(16) uint8_t sW[2][WTILE];   // A tiles (hi|lo), 20KB
    __shared__ __align__(16) uint8_t sS[2][WTILE];   // B tiles (hi|lo), 20KB

    int blk = blockIdx.x;               // Bn*(Pn/128) = 256
    int b  = blk >> 7;
    int p0 = (blk & 127) * 128;
    int t  = threadIdx.x;
    int w  = t >> 5, l = t & 31;
    int ow = w >> 1, nh = w & 1;
    int vv = t >> 2, q = t & 3;

    float dacc[8][4];                   // 16 o x 64 v per warp
    #pragma unroll
    for (int n = 0; n < 8; ++n)
        #pragma unroll
        for (int j = 0; j < 4; ++j) dacc[n][j] = 0.f;

    const size_t offB = (size_t)b * NOFF * Pn;
    const float* upB  = g_up_cl + (size_t)b*Pn*CSn;

    int p = p0 + vv;
    int dg = p >> 10, hg = (p >> 5) & 31, wg = p & 31;

    // ---- sampling (1 voxel/thread) + W staging for tap kk -> buf ----
    auto sample = [&](int kk, int buf) {
        int g = kk / K3n, k = kk % K3n;
        int kz = k/9 - 1, ky = (k/3)%3 - 1, kx = k%3 - 1;
        int ob = (g*K3n + k)*3;
        const float* upg = upB + g*CGn + q*4;

        float z = dg + kz + g_off[offB + (size_t)(ob+0)*Pn + p];
        float y = hg + ky + g_off[offB + (size_t)(ob+1)*Pn + p];
        float x = wg + kx + g_off[offB + (size_t)(ob+2)*Pn + p];

        float z0f = floorf(z), y0f = floorf(y), x0f = floorf(x);
        float fz = z - z0f, fy = y - y0f, fx = x - x0f;
        int z0 = (int)z0f, y0 = (int)y0f, x0 = (int)x0f;

        float4 sa = make_float4(0.f, 0.f, 0.f, 0.f);
        #pragma unroll
        for (int cnr = 0; cnr < 8; ++cnr) {
            int dz = cnr>>2, dy = (cnr>>1)&1, dx = cnr&1;
            int iz = z0+dz, iy = y0+dy, ix = x0+dx;
            float wt = (dz ? fz : 1.f-fz) * (dy ? fy : 1.f-fy) * (dx ? fx : 1.f-fx);
            bool ok = (iz>=0) & (iz<DDn) & (iy>=0) & (iy<DHn) & (ix>=0) & (ix<DWn);
            wt = ok ? wt : 0.f;
            int ci = min(max(iz,0),DDn-1)*1024 + min(max(iy,0),DHn-1)*32 + min(max(ix,0),DWn-1);
            float4 v = *(const float4*)(upg + (size_t)ci*CSn);
            sa.x += wt*v.x; sa.y += wt*v.y; sa.z += wt*v.z; sa.w += wt*v.w;
        }
        // bf16 split: hi + lo
        __nv_bfloat16 h0 = __float2bfloat16(sa.x);
        __nv_bfloat16 h1 = __float2bfloat16(sa.y);
        __nv_bfloat16 h2 = __float2bfloat16(sa.z);
        __nv_bfloat16 h3 = __float2bfloat16(sa.w);
        __nv_bfloat16 l0 = __float2bfloat16(sa.x - __bfloat162float(h0));
        __nv_bfloat16 l1 = __float2bfloat16(sa.y - __bfloat162float(h1));
        __nv_bfloat16 l2 = __float2bfloat16(sa.z - __bfloat162float(h2));
        __nv_bfloat16 l3 = __float2bfloat16(sa.w - __bfloat162float(h3));
        uint8_t* rowp = sS[buf] + vv*WROW + q*8;
        *(uint2*)rowp        = make_uint2(packbf(h0,h1), packbf(h2,h3));
        *(uint2*)(rowp + 32) = make_uint2(packbf(l0,l1), packbf(l2,l3));

        // stage pre-split W tile (10240 B = 640 uint4) for this tap
        const uint4* srcW = (const uint4*)(g_wsplit + (size_t)kk*WTILE);
        uint4* dstW = (uint4*)sW[buf];
        dstW[t] = srcW[t];
        if (t < WTILE/16 - 512) dstW[t + 512] = srcW[t + 512];
    };

    // ---- tensor GEMM on buffer buf ----
    auto domma = [&](int buf) {
        uint32_t sWb = (uint32_t)__cvta_generic_to_shared(&sW[buf][0]);
        uint32_t sSb = (uint32_t)__cvta_generic_to_shared(&sS[buf][0]);
        uint32_t aaddr = sWb + (ow*16 + (l & 15))*WROW + (l >> 4)*16;
        uint32_t ah[4], al[4];
        ldsm4(ah, aaddr);
        ldsm4(al, aaddr + 32);
        uint32_t brow = 8*(l >> 4) + (l & 7);
        uint32_t bcol = ((l >> 3) & 1)*16;
        #pragma unroll
        for (int nc = 0; nc < 4; ++nc) {
            uint32_t baddr = sSb + (nh*64 + nc*16 + brow)*WROW + bcol;
            uint32_t bh[4], bl[4];
            ldsm4(bh, baddr);
            ldsm4(bl, baddr + 32);
            // D += Wh*Sh + Wh*Sl + Wl*Sh   (fp32 accumulate)
            mma16816(dacc[2*nc  ], ah, bh[0], bh[1]);
            mma16816(dacc[2*nc  ], ah, bl[0], bl[1]);
            mma16816(dacc[2*nc  ], al, bh[0], bh[1]);
            mma16816(dacc[2*nc+1], ah, bh[2], bh[3]);
            mma16816(dacc[2*nc+1], ah, bl[2], bl[3]);
            mma16816(dacc[2*nc+1], al, bh[2], bh[3]);
        }
    };

    sample(0, 0);
    __syncthreads();

    for (int kk = 0; kk < NTAP; ++kk) {
        int cur = kk & 1;
        domma(cur);
        if (kk + 1 < NTAP) sample(kk + 1, cur ^ 1);
        __syncthreads();
    }

    // ---- epilogue: ReLU + STG.64 ----
    int g = l >> 2, tq = l & 3;
    size_t base0 = ((size_t)b*CDn + ow*16 + g)*Pn + p0 + nh*64 + 2*tq;
    size_t base1 = base0 + (size_t)8*Pn;
    #pragma unroll
    for (int n = 0; n < 8; ++n) {
        float2 v0 = make_float2(fmaxf(dacc[n][0], 0.f), fmaxf(dacc[n][1], 0.f));
        float2 v1 = make_float2(fmaxf(dacc[n][2], 0.f), fmaxf(dacc[n][3], 0.f));
        *(float2*)&out[base0 + n*8] = v0;
        *(float2*)&out[base1 + n*8] = v1;
    }
}

extern "C" void kernel_launch(void* const* d_in, const int* in_sizes, int n_in,
                              void* d_out, int out_size) {
    const float* src  = (const float*)d_in[0];   // feat_1x_src [2,128,8,16,16]
    const float* dst  = (const float*)d_in[1];   // feat_2x_dst [2,128,16,32,32]
    const float* woff = (const float*)d_in[2];   // w_offset [648,256]
    const float* wdcn = (const float*)d_in[3];   // w_dcn [128,128,3,3,3]
    float* out = (float*)d_out;

    const int NPREP = Bn*SDn*SHn*SWn*CSn + 256*NOFF + NTAP*128*CGn;
    k_prep     <<<(NPREP + 255)/256, 256>>>(src, woff, wdcn);
    k_upsample <<<Bn*Pn, 128>>>();
    k_offset   <<<Bn*(Pn/32), 256>>>(dst);
    k_dcn      <<<Bn*(Pn/128), 512>>>(out);
}

// round 8
// speedup vs baseline: 1.7779x; 1.0796x over previous
#include <cuda_runtime.h>
#include <cuda_bf16.h>
#include <cstdint>

#define Bn 2
#define CSn 128
#define CDn 128
#define SDn 8
#define SHn 16
#define SWn 16
#define DDn 16
#define DHn 32
#define DWn 32
#define Pn  (DDn*DHn*DWn)      /* 16384 */
#define Gn 8
#define K3n 27
#define CGn 16                 /* CS/G */
#define NOFF (K3n*3*Gn)        /* 648 */
#define NTAP (Gn*K3n)          /* 216 */
#define WROW 80                /* padded row bytes of A/B smem tiles */
#define WTILE (128*WROW)       /* 10240 B per tap weight tile */
#define STILE (64*WROW)        /* 5120 B per tap sample tile */

typedef unsigned long long ull;

// ---------------- f32x2 helpers ---------------------------------------------
__device__ __forceinline__ ull ffma2(ull a, ull b, ull c) {
    ull d;
    asm("fma.rn.f32x2 %0, %1, %2, %3;" : "=l"(d) : "l"(a), "l"(b), "l"(c));
    return d;
}
__device__ __forceinline__ ull dup2(float s) {
    ull d;
    unsigned u = __float_as_uint(s);
    asm("mov.b64 %0, {%1, %1};" : "=l"(d) : "r"(u));
    return d;
}
__device__ __forceinline__ float lo32(ull v) {
    return __uint_as_float((unsigned)(v & 0xffffffffull));
}
__device__ __forceinline__ float hi32(ull v) {
    return __uint_as_float((unsigned)(v >> 32));
}

// ---------------- tensor-core helpers ---------------------------------------
__device__ __forceinline__ void ldsm4(uint32_t* r, uint32_t addr) {
    asm volatile("ldmatrix.sync.aligned.m8n8.x4.shared.b16 {%0,%1,%2,%3},[%4];"
        : "=r"(r[0]), "=r"(r[1]), "=r"(r[2]), "=r"(r[3]) : "r"(addr));
}
__device__ __forceinline__ void mma16816(float* d, const uint32_t* a,
                                         uint32_t b0, uint32_t b1) {
    asm volatile(
        "mma.sync.aligned.m16n8k16.row.col.f32.bf16.bf16.f32 "
        "{%0,%1,%2,%3},{%4,%5,%6,%7},{%8,%9},{%0,%1,%2,%3};"
        : "+f"(d[0]), "+f"(d[1]), "+f"(d[2]), "+f"(d[3])
        : "r"(a[0]), "r"(a[1]), "r"(a[2]), "r"(a[3]), "r"(b0), "r"(b1));
}
__device__ __forceinline__ uint32_t packbf(__nv_bfloat16 a, __nv_bfloat16 b) {
    __nv_bfloat162 t = __halves2bfloat162(a, b);
    return *(uint32_t*)&t;
}

// -------- device scratch ----------------------------------------------------
__device__ float g_src_cl[Bn*SDn*SHn*SWn*CSn];   // [b][z][y][x][c]
__device__ float g_up_cl[Bn*Pn*CSn];             // [b][p][c]
__device__ float g_off[Bn*NOFF*Pn];              // [b][o][p]
__device__ float g_wofft[256*NOFF];              // [c][o]
__device__ __align__(16) uint8_t g_wsplit[(size_t)NTAP*WTILE]; // bf16 hi/lo image

// -------- prep: all transposes + bf16 weight split --------------------------
__global__ void k_prep(const float* __restrict__ src,
                       const float* __restrict__ woff,
                       const float* __restrict__ wdcn) {
    int i = blockIdx.x * blockDim.x + threadIdx.x;
    const int N1 = Bn*SDn*SHn*SWn*CSn;    // 524288
    const int N2 = 256*NOFF;              // 165888
    const int N3 = NTAP*128*CGn;          // 442368
    if (i < N1) {
        int c = i % CSn;
        int s = (i / CSn) % (SDn*SHn*SWn);
        int b = i / (CSn*SDn*SHn*SWn);
        g_src_cl[i] = src[(b*CSn + c)*(SDn*SHn*SWn) + s];
    } else if (i < N1 + N2) {
        int j = i - N1;
        int o = j % NOFF;
        int c = j / NOFF;
        g_wofft[j] = woff[o*256 + c];
    } else if (i < N1 + N2 + N3) {
        int j = i - N1 - N2;
        int cg = j % CGn;
        int o  = (j / CGn) % 128;
        int kk = j / (CGn*128);
        int g = kk / K3n, k = kk % K3n;
        float wv = wdcn[((o*CSn) + g*CGn + cg)*K3n + k];
        __nv_bfloat16 hb = __float2bfloat16(wv);
        __nv_bfloat16 lb = __float2bfloat16(wv - __bfloat162float(hb));
        uint8_t* row = g_wsplit + (size_t)kk*WTILE + o*WROW;
        *(__nv_bfloat16*)(row + cg*2)      = hb;
        *(__nv_bfloat16*)(row + 32 + cg*2) = lb;
    }
}

// -------- trilinear 2x upsample ----------------------------------------------
__global__ void k_upsample() {
    int bp = blockIdx.x;                 // Bn*Pn blocks
    int b = bp / Pn;
    int p = bp % Pn;
    int d = p >> 10, h = (p >> 5) & 31, w = p & 31;

    float zc = d*0.5f - 0.25f, yc = h*0.5f - 0.25f, xc = w*0.5f - 0.25f;
    int zf = (int)floorf(zc), yf = (int)floorf(yc), xf = (int)floorf(xc);
    float fz = zc - zf, fy = yc - yf, fx = xc - xf;
    int z0 = min(max(zf,     0), SDn-1), z1 = min(max(zf + 1, 0), SDn-1);
    int y0 = min(max(yf,     0), SHn-1), y1 = min(max(yf + 1, 0), SHn-1);
    int x0 = min(max(xf,     0), SWn-1), x1 = min(max(xf + 1, 0), SWn-1);

    const float* base = g_src_cl + (size_t)b * (SDn*SHn*SWn) * CSn;
    int c = threadIdx.x;  // 128

    float v000 = base[(z0*256 + y0*16 + x0)*CSn + c];
    float v001 = base[(z0*256 + y0*16 + x1)*CSn + c];
    float v010 = base[(z0*256 + y1*16 + x0)*CSn + c];
    float v011 = base[(z0*256 + y1*16 + x1)*CSn + c];
    float v100 = base[(z1*256 + y0*16 + x0)*CSn + c];
    float v101 = base[(z1*256 + y0*16 + x1)*CSn + c];
    float v110 = base[(z1*256 + y1*16 + x0)*CSn + c];
    float v111 = base[(z1*256 + y1*16 + x1)*CSn + c];

    float r0 = (1.f-fy)*((1.f-fx)*v000 + fx*v001) + fy*((1.f-fx)*v010 + fx*v011);
    float r1 = (1.f-fy)*((1.f-fx)*v100 + fx*v101) + fy*((1.f-fx)*v110 + fx*v111);
    g_up_cl[((size_t)b*Pn + p)*CSn + c] = (1.f-fz)*r0 + fz*r1;
}

// -------- 1x1 offset conv (FFMA2, unchanged) ---------------------------------
__global__ void __launch_bounds__(256) k_offset(const float* __restrict__ dst) {
    __shared__ __align__(16) float cat_s[256*32];     // [c][v] 32KB
    int blk = blockIdx.x;               // Bn*(Pn/32)
    int b  = blk / (Pn/32);
    int p0 = (blk % (Pn/32)) * 32;
    int t = threadIdx.x;

    for (int i = t; i < 128*32; i += 256) {
        int c = i >> 5, v = i & 31;
        cat_s[i] = dst[((size_t)b*CDn + c)*Pn + p0 + v];
    }
    for (int i = t; i < 32*128; i += 256) {
        int v = i >> 7, c = i & 127;
        cat_s[(128 + c)*32 + v] = 2.0f * g_up_cl[((size_t)b*Pn + p0 + v)*CSn + c];
    }
    __syncthreads();

    int og = t >> 3;
    int vg = t & 7;
    int v0 = vg * 4;

    #pragma unroll
    for (int pass = 0; pass < 3; ++pass) {
        int o0 = pass*256 + og*8;
        if (o0 >= NOFF) break;
        ull a[4][4];
        #pragma unroll
        for (int i = 0; i < 4; ++i)
            #pragma unroll
            for (int j = 0; j < 4; ++j) a[i][j] = 0ull;

        #pragma unroll 4
        for (int c = 0; c < 256; ++c) {
            const ulonglong2* wrow = (const ulonglong2*)&g_wofft[c*NOFF + o0];
            ulonglong2 wA = wrow[0];
            ulonglong2 wB = wrow[1];
            float4 sv = *(const float4*)&cat_s[c*32 + v0];
            ull s0 = dup2(sv.x), s1 = dup2(sv.y);
            ull s2 = dup2(sv.z), s3 = dup2(sv.w);
            a[0][0] = ffma2(wA.x, s0, a[0][0]); a[0][1] = ffma2(wA.x, s1, a[0][1]);
            a[0][2] = ffma2(wA.x, s2, a[0][2]); a[0][3] = ffma2(wA.x, s3, a[0][3]);
            a[1][0] = ffma2(wA.y, s0, a[1][0]); a[1][1] = ffma2(wA.y, s1, a[1][1]);
            a[1][2] = ffma2(wA.y, s2, a[1][2]); a[1][3] = ffma2(wA.y, s3, a[1][3]);
            a[2][0] = ffma2(wB.x, s0, a[2][0]); a[2][1] = ffma2(wB.x, s1, a[2][1]);
            a[2][2] = ffma2(wB.x, s2, a[2][2]); a[2][3] = ffma2(wB.x, s3, a[2][3]);
            a[3][0] = ffma2(wB.y, s0, a[3][0]); a[3][1] = ffma2(wB.y, s1, a[3][1]);
            a[3][2] = ffma2(wB.y, s2, a[3][2]); a[3][3] = ffma2(wB.y, s3, a[3][3]);
        }

        #pragma unroll
        for (int op = 0; op < 4; ++op) {
            float4 flo = make_float4(lo32(a[op][0]), lo32(a[op][1]),
                                     lo32(a[op][2]), lo32(a[op][3]));
            float4 fhi = make_float4(hi32(a[op][0]), hi32(a[op][1]),
                                     hi32(a[op][2]), hi32(a[op][3]));
            size_t base = ((size_t)b*NOFF + o0 + op*2)*Pn + p0 + v0;
            *(float4*)&g_off[base]              = flo;
            *(float4*)&g_off[base + (size_t)Pn] = fhi;
        }
    }
}

// -------- fused deformable sampling + bf16-split tensor GEMM + ReLU ---------
// block: 64 voxels, 256 threads / 8 warps, 2 CTAs/SM.
// sampling: (vv = t>>2, q = t&3) -> one voxel, 4 channels of group g
// mma: warp w -> o-strip w (16 rows) x all 64 voxels.
__global__ void __launch_bounds__(256, 2) k_dcn(float* __restrict__ out) {
    __shared__ __align__(16) uint8_t sW[2][WTILE];   // A tiles (hi|lo), 20KB
    __shared__ __align__(16) uint8_t sS[2][STILE];   // B tiles (hi|lo), 10KB

    int blk = blockIdx.x;               // Bn*(Pn/64) = 512
    int b  = blk >> 8;
    int p0 = (blk & 255) * 64;
    int t  = threadIdx.x;
    int w  = t >> 5, l = t & 31;
    int vv = t >> 2, q = t & 3;

    float dacc[8][4];                   // 16 o x 64 v per warp
    #pragma unroll
    for (int n = 0; n < 8; ++n)
        #pragma unroll
        for (int j = 0; j < 4; ++j) dacc[n][j] = 0.f;

    const size_t offB = (size_t)b * NOFF * Pn;
    const float* upB  = g_up_cl + (size_t)b*Pn*CSn;
    const float* upg4 = upB + q*4;      // + g*CGn at use

    int p = p0 + vv;
    int dg = p >> 10, hg = (p >> 5) & 31, wg = p & 31;

    // ---- load offsets for tap kk (3 LDG, issued early) ----
    auto loadoffs = [&](int kk, float& z, float& y, float& x) {
        int g = kk / K3n, k = kk % K3n;
        int kz = k/9 - 1, ky = (k/3)%3 - 1, kx = k%3 - 1;
        size_t ob = offB + (size_t)(g*K3n + k)*3*Pn + p;
        z = dg + kz + g_off[ob];
        y = hg + ky + g_off[ob + Pn];
        x = wg + kx + g_off[ob + 2*Pn];
    };

    // ---- gather + bf16-split store for tap kk into buf ----
    auto gather = [&](int kk, float z, float y, float x, int buf) {
        int g = kk / K3n;
        const float* upg = upg4 + g*CGn;

        float z0f = floorf(z), y0f = floorf(y), x0f = floorf(x);
        float fz = z - z0f, fy = y - y0f, fx = x - x0f;
        int z0 = (int)z0f, y0 = (int)y0f, x0 = (int)x0f;

        // per-axis clamped indices + validity-zeroed weights
        float wz0 = (z0   >= 0 && z0   < DDn) ? 1.f - fz : 0.f;
        float wz1 = (z0+1 >= 0 && z0+1 < DDn) ? fz       : 0.f;
        float wy0 = (y0   >= 0 && y0   < DHn) ? 1.f - fy : 0.f;
        float wy1 = (y0+1 >= 0 && y0+1 < DHn) ? fy       : 0.f;
        float wx0 = (x0   >= 0 && x0   < DWn) ? 1.f - fx : 0.f;
        float wx1 = (x0+1 >= 0 && x0+1 < DWn) ? fx       : 0.f;
        int zi0 = min(max(z0,   0), DDn-1) << 10;
        int zi1 = min(max(z0+1, 0), DDn-1) << 10;
        int yi0 = min(max(y0,   0), DHn-1) << 5;
        int yi1 = min(max(y0+1, 0), DHn-1) << 5;
        int xi0 = min(max(x0,   0), DWn-1);
        int xi1 = min(max(x0+1, 0), DWn-1);
        float w00 = wz0*wy0, w01 = wz0*wy1, w10 = wz1*wy0, w11 = wz1*wy1;
        int   i00 = zi0+yi0, i01 = zi0+yi1, i10 = zi1+yi0, i11 = zi1+yi1;

        float4 sa = make_float4(0.f, 0.f, 0.f, 0.f);
        #pragma unroll
        for (int cnr = 0; cnr < 8; ++cnr) {
            float wzy = (cnr>>2) ? ((cnr>>1)&1 ? w11 : w10) : ((cnr>>1)&1 ? w01 : w00);
            int   izy = (cnr>>2) ? ((cnr>>1)&1 ? i11 : i10) : ((cnr>>1)&1 ? i01 : i00);
            float wt  = wzy * ((cnr&1) ? wx1 : wx0);
            int   ci  = izy + ((cnr&1) ? xi1 : xi0);
            float4 v = *(const float4*)(upg + (size_t)ci*CSn);
            sa.x += wt*v.x; sa.y += wt*v.y; sa.z += wt*v.z; sa.w += wt*v.w;
        }
        __nv_bfloat16 h0 = __float2bfloat16(sa.x);
        __nv_bfloat16 h1 = __float2bfloat16(sa.y);
        __nv_bfloat16 h2 = __float2bfloat16(sa.z);
        __nv_bfloat16 h3 = __float2bfloat16(sa.w);
        __nv_bfloat16 l0 = __float2bfloat16(sa.x - __bfloat162float(h0));
        __nv_bfloat16 l1 = __float2bfloat16(sa.y - __bfloat162float(h1));
        __nv_bfloat16 l2 = __float2bfloat16(sa.z - __bfloat162float(h2));
        __nv_bfloat16 l3 = __float2bfloat16(sa.w - __bfloat162float(h3));
        uint8_t* rowp = sS[buf] + vv*WROW + q*8;
        *(uint2*)rowp        = make_uint2(packbf(h0,h1), packbf(h2,h3));
        *(uint2*)(rowp + 32) = make_uint2(packbf(l0,l1), packbf(l2,l3));
    };

    // ---- tensor GEMM on buffer buf ----
    auto domma = [&](int buf) {
        uint32_t sWb = (uint32_t)__cvta_generic_to_shared(&sW[buf][0]);
        uint32_t sSb = (uint32_t)__cvta_generic_to_shared(&sS[buf][0]);
        uint32_t aaddr = sWb + (w*16 + (l & 15))*WROW + (l >> 4)*16;
        uint32_t ah[4], al[4];
        ldsm4(ah, aaddr);
        ldsm4(al, aaddr + 32);
        uint32_t brow = 8*(l >> 4) + (l & 7);
        uint32_t bcol = ((l >> 3) & 1)*16;
        #pragma unroll
        for (int nc = 0; nc < 4; ++nc) {
            uint32_t baddr = sSb + (nc*16 + brow)*WROW + bcol;
            uint32_t bh[4], bl[4];
            ldsm4(bh, baddr);
            ldsm4(bl, baddr + 32);
            mma16816(dacc[2*nc  ], ah, bh[0], bh[1]);
            mma16816(dacc[2*nc  ], ah, bl[0], bl[1]);
            mma16816(dacc[2*nc  ], al, bh[0], bh[1]);
            mma16816(dacc[2*nc+1], ah, bh[2], bh[3]);
            mma16816(dacc[2*nc+1], ah, bl[2], bl[3]);
            mma16816(dacc[2*nc+1], al, bh[2], bh[3]);
        }
    };

    // ---- prologue: tap 0 ----
    {
        float z, y, x;
        loadoffs(0, z, y, x);
        gather(0, z, y, x, 0);
        const uint4* srcW = (const uint4*)(g_wsplit);
        uint4* dstW = (uint4*)sW[0];
        dstW[t] = srcW[t];
        dstW[t + 256] = srcW[t + 256];
        if (t < WTILE/16 - 512) dstW[t + 512] = srcW[t + 512];
    }
    __syncthreads();

    for (int kk = 0; kk < NTAP; ++kk) {
        int cur = kk & 1;

        float z, y, x;
        uint4 wr0, wr1, wr2;
        bool more = (kk + 1 < NTAP);
        if (more) {
            // prefetch next tap's offsets + weight tile into regs (hidden by mma)
            loadoffs(kk + 1, z, y, x);
            const uint4* srcW = (const uint4*)(g_wsplit + (size_t)(kk+1)*WTILE);
            wr0 = srcW[t];
            wr1 = srcW[t + 256];
            if (t < WTILE/16 - 512) wr2 = srcW[t + 512];
        }

        domma(cur);

        if (more) {
            int nb = cur ^ 1;
            uint4* dstW = (uint4*)sW[nb];
            dstW[t] = wr0;
            dstW[t + 256] = wr1;
            if (t < WTILE/16 - 512) dstW[t + 512] = wr2;
            gather(kk + 1, z, y, x, nb);
        }
        __syncthreads();
    }

    // ---- epilogue: ReLU + STG.64 ----
    int g = l >> 2, tq = l & 3;
    size_t base0 = ((size_t)b*CDn + w*16 + g)*Pn + p0 + 2*tq;
    size_t base1 = base0 + (size_t)8*Pn;
    #pragma unroll
    for (int n = 0; n < 8; ++n) {
        float2 v0 = make_float2(fmaxf(dacc[n][0], 0.f), fmaxf(dacc[n][1], 0.f));
        float2 v1 = make_float2(fmaxf(dacc[n][2], 0.f), fmaxf(dacc[n][3], 0.f));
        *(float2*)&out[base0 + n*8] = v0;
        *(float2*)&out[base1 + n*8] = v1;
    }
}

extern "C" void kernel_launch(void* const* d_in, const int* in_sizes, int n_in,
                              void* d_out, int out_size) {
    const float* src  = (const float*)d_in[0];   // feat_1x_src [2,128,8,16,16]
    const float* dst  = (const float*)d_in[1];   // feat_2x_dst [2,128,16,32,32]
    const float* woff = (const float*)d_in[2];   // w_offset [648,256]
    const float* wdcn = (const float*)d_in[3];   // w_dcn [128,128,3,3,3]
    float* out = (float*)d_out;

    const int NPREP = Bn*SDn*SHn*SWn*CSn + 256*NOFF + NTAP*128*CGn;
    k_prep     <<<(NPREP + 255)/256, 256>>>(src, woff, wdcn);
    k_upsample <<<Bn*Pn, 128>>>();
    k_offset   <<<Bn*(Pn/32), 256>>>(dst);
    k_dcn      <<<Bn*(Pn/64), 256>>>(out);
}

// round 9
// speedup vs baseline: 2.0898x; 1.1754x over previous
#include <cuda_runtime.h>
#include <cuda_bf16.h>
#include <cstdint>

#define Bn 2
#define CSn 128
#define CDn 128
#define SDn 8
#define SHn 16
#define SWn 16
#define DDn 16
#define DHn 32
#define DWn 32
#define Pn  (DDn*DHn*DWn)      /* 16384 */
#define Gn 8
#define K3n 27
#define CGn 16                 /* CS/G */
#define NOFF (K3n*3*Gn)        /* 648 */
#define NTAP (Gn*K3n)          /* 216 */
#define WROW 80                /* padded row bytes of A/B smem tiles */
#define WTILE (128*WROW)       /* 10240 B per weight tile */
#define STILE (64*WROW)        /* 5120 B per sample tile */
#define MTILES 6               /* ceil(648/128) m-tiles for offset GEMM */

// ---------------- tensor-core helpers ---------------------------------------
__device__ __forceinline__ void ldsm4(uint32_t* r, uint32_t addr) {
    asm volatile("ldmatrix.sync.aligned.m8n8.x4.shared.b16 {%0,%1,%2,%3},[%4];"
        : "=r"(r[0]), "=r"(r[1]), "=r"(r[2]), "=r"(r[3]) : "r"(addr));
}
__device__ __forceinline__ void mma16816(float* d, const uint32_t* a,
                                         uint32_t b0, uint32_t b1) {
    asm volatile(
        "mma.sync.aligned.m16n8k16.row.col.f32.bf16.bf16.f32 "
        "{%0,%1,%2,%3},{%4,%5,%6,%7},{%8,%9},{%0,%1,%2,%3};"
        : "+f"(d[0]), "+f"(d[1]), "+f"(d[2]), "+f"(d[3])
        : "r"(a[0]), "r"(a[1]), "r"(a[2]), "r"(a[3]), "r"(b0), "r"(b1));
}
__device__ __forceinline__ uint32_t packbf(__nv_bfloat16 a, __nv_bfloat16 b) {
    __nv_bfloat162 t = __halves2bfloat162(a, b);
    return *(uint32_t*)&t;
}

// -------- device scratch ----------------------------------------------------
__device__ float g_src_cl[Bn*SDn*SHn*SWn*CSn];   // [b][z][y][x][c]
__device__ float g_up_cl[Bn*Pn*CSn];             // [b][p][c]
__device__ float g_off[Bn*NOFF*Pn];              // [b][o][p]
__device__ __align__(16) uint8_t g_wsplit[(size_t)NTAP*WTILE];       // dcn W hi/lo
__device__ __align__(16) uint8_t g_wosplit[(size_t)MTILES*16*WTILE]; // offset W hi/lo
__device__ __align__(16) __nv_bfloat16 g_cath[(size_t)Bn*Pn*256];    // cat hi [b][p][c]
__device__ __align__(16) __nv_bfloat16 g_catl[(size_t)Bn*Pn*256];    // cat lo

// -------- prep: transposes + bf16 weight splits ------------------------------
__global__ void k_prep(const float* __restrict__ src,
                       const float* __restrict__ woff,
                       const float* __restrict__ wdcn) {
    int i = blockIdx.x * blockDim.x + threadIdx.x;
    const int N1 = Bn*SDn*SHn*SWn*CSn;    // 524288
    const int N3 = NTAP*128*CGn;          // 442368
    const int N4 = MTILES*128*256;        // 196608 (768 o x 256 c)
    if (i < N1) {
        int c = i % CSn;
        int s = (i / CSn) % (SDn*SHn*SWn);
        int b = i / (CSn*SDn*SHn*SWn);
        g_src_cl[i] = src[(b*CSn + c)*(SDn*SHn*SWn) + s];
    } else if (i < N1 + N3) {
        int j = i - N1;
        int cg = j % CGn;
        int o  = (j / CGn) % 128;
        int kk = j / (CGn*128);
        int g = kk / K3n, k = kk % K3n;
        float wv = wdcn[((o*CSn) + g*CGn + cg)*K3n + k];
        __nv_bfloat16 hb = __float2bfloat16(wv);
        __nv_bfloat16 lb = __float2bfloat16(wv - __bfloat162float(hb));
        uint8_t* row = g_wsplit + (size_t)kk*WTILE + o*WROW;
        *(__nv_bfloat16*)(row + cg*2)      = hb;
        *(__nv_bfloat16*)(row + 32 + cg*2) = lb;
    } else if (i < N1 + N3 + N4) {
        int j = i - N1 - N3;
        int c = j % 256;
        int o = j / 256;                  // 0..767 (padded)
        float wv = (o < NOFF) ? woff[o*256 + c] : 0.f;
        __nv_bfloat16 hb = __float2bfloat16(wv);
        __nv_bfloat16 lb = __float2bfloat16(wv - __bfloat162float(hb));
        int mt = o >> 7, kc = c >> 4;
        uint8_t* row = g_wosplit + (size_t)(mt*16 + kc)*WTILE + (o & 127)*WROW;
        *(__nv_bfloat16*)(row + (c & 15)*2)      = hb;
        *(__nv_bfloat16*)(row + 32 + (c & 15)*2) = lb;
    }
}

// -------- trilinear 2x upsample ----------------------------------------------
__global__ void k_upsample() {
    int bp = blockIdx.x;                 // Bn*Pn blocks
    int b = bp / Pn;
    int p = bp % Pn;
    int d = p >> 10, h = (p >> 5) & 31, w = p & 31;

    float zc = d*0.5f - 0.25f, yc = h*0.5f - 0.25f, xc = w*0.5f - 0.25f;
    int zf = (int)floorf(zc), yf = (int)floorf(yc), xf = (int)floorf(xc);
    float fz = zc - zf, fy = yc - yf, fx = xc - xf;
    int z0 = min(max(zf,     0), SDn-1), z1 = min(max(zf + 1, 0), SDn-1);
    int y0 = min(max(yf,     0), SHn-1), y1 = min(max(yf + 1, 0), SHn-1);
    int x0 = min(max(xf,     0), SWn-1), x1 = min(max(xf + 1, 0), SWn-1);

    const float* base = g_src_cl + (size_t)b * (SDn*SHn*SWn) * CSn;
    int c = threadIdx.x;  // 128

    float v000 = base[(z0*256 + y0*16 + x0)*CSn + c];
    float v001 = base[(z0*256 + y0*16 + x1)*CSn + c];
    float v010 = base[(z0*256 + y1*16 + x0)*CSn + c];
    float v011 = base[(z0*256 + y1*16 + x1)*CSn + c];
    float v100 = base[(z1*256 + y0*16 + x0)*CSn + c];
    float v101 = base[(z1*256 + y0*16 + x1)*CSn + c];
    float v110 = base[(z1*256 + y1*16 + x0)*CSn + c];
    float v111 = base[(z1*256 + y1*16 + x1)*CSn + c];

    float r0 = (1.f-fy)*((1.f-fx)*v000 + fx*v001) + fy*((1.f-fx)*v010 + fx*v011);
    float r1 = (1.f-fy)*((1.f-fx)*v100 + fx*v101) + fy*((1.f-fx)*v110 + fx*v111);
    g_up_cl[((size_t)b*Pn + p)*CSn + c] = (1.f-fz)*r0 + fz*r1;
}

// -------- build pre-split bf16 cat image [b][p][256c] ------------------------
__global__ void __launch_bounds__(256) k_cat(const float* __restrict__ dst) {
    __shared__ float cat_s[256*33];     // padded to kill bank conflicts
    int blk = blockIdx.x;               // Bn*(Pn/32)
    int b  = blk / (Pn/32);
    int p0 = (blk % (Pn/32)) * 32;
    int t = threadIdx.x;

    for (int i = t; i < 128*32; i += 256) {
        int c = i >> 5, v = i & 31;
        cat_s[c*33 + v] = dst[((size_t)b*CDn + c)*Pn + p0 + v];
    }
    for (int i = t; i < 32*128; i += 256) {
        int v = i >> 7, c = i & 127;
        cat_s[(128 + c)*33 + v] = 2.0f * g_up_cl[((size_t)b*Pn + p0 + v)*CSn + c];
    }
    __syncthreads();

    int v = t & 31, cg = t >> 5;        // 8 groups of 32 channels
    uint32_t oh[16], ol[16];
    #pragma unroll
    for (int j = 0; j < 16; ++j) {
        float f0 = cat_s[(cg*32 + 2*j    )*33 + v];
        float f1 = cat_s[(cg*32 + 2*j + 1)*33 + v];
        __nv_bfloat16 h0 = __float2bfloat16(f0);
        __nv_bfloat16 h1 = __float2bfloat16(f1);
        __nv_bfloat16 l0 = __float2bfloat16(f0 - __bfloat162float(h0));
        __nv_bfloat16 l1 = __float2bfloat16(f1 - __bfloat162float(h1));
        oh[j] = packbf(h0, h1);
        ol[j] = packbf(l0, l1);
    }
    size_t base = ((size_t)b*Pn + p0 + v)*256 + cg*32;
    uint4* dh = (uint4*)&g_cath[base];
    uint4* dl = (uint4*)&g_catl[base];
    #pragma unroll
    for (int j = 0; j < 4; ++j) {
        dh[j] = make_uint4(oh[4*j], oh[4*j+1], oh[4*j+2], oh[4*j+3]);
        dl[j] = make_uint4(ol[4*j], ol[4*j+1], ol[4*j+2], ol[4*j+3]);
    }
}

// -------- offset GEMM on tensor cores: g_off[b,o,p] --------------------------
// block: 128 o x 64 p, 256 threads / 8 warps; K=256 in 16 chunks.
__global__ void __launch_bounds__(256, 2) k_offmma() {
    __shared__ __align__(16) uint8_t sW[2][WTILE];   // 20KB
    __shared__ __align__(16) uint8_t sS[2][STILE];   // 10KB

    int blk = blockIdx.x;               // Bn*MTILES*(Pn/64) = 3072
    int b  = blk / (MTILES*256);
    int r  = blk % (MTILES*256);
    int mt = r / 256;
    int p0 = (r % 256) * 64;
    int t  = threadIdx.x;
    int w  = t >> 5, l = t & 31;

    float dacc[8][4];
    #pragma unroll
    for (int n = 0; n < 8; ++n)
        #pragma unroll
        for (int j = 0; j < 4; ++j) dacc[n][j] = 0.f;

    int brow = t >> 1, bpart = t & 1;   // B staging map (t<128)
    const __nv_bfloat16* catsrc = (bpart ? g_catl : g_cath)
                                + ((size_t)b*Pn + p0 + brow)*256;

    auto domma = [&](int buf) {
        uint32_t sWb = (uint32_t)__cvta_generic_to_shared(&sW[buf][0]);
        uint32_t sSb = (uint32_t)__cvta_generic_to_shared(&sS[buf][0]);
        uint32_t aaddr = sWb + (w*16 + (l & 15))*WROW + (l >> 4)*16;
        uint32_t ah[4], al[4];
        ldsm4(ah, aaddr);
        ldsm4(al, aaddr + 32);
        uint32_t br = 8*(l >> 4) + (l & 7);
        uint32_t bc = ((l >> 3) & 1)*16;
        #pragma unroll
        for (int nc = 0; nc < 4; ++nc) {
            uint32_t baddr = sSb + (nc*16 + br)*WROW + bc;
            uint32_t bh[4], bl[4];
            ldsm4(bh, baddr);
            ldsm4(bl, baddr + 32);
            mma16816(dacc[2*nc  ], ah, bh[0], bh[1]);
            mma16816(dacc[2*nc  ], ah, bl[0], bl[1]);
            mma16816(dacc[2*nc  ], al, bh[0], bh[1]);
            mma16816(dacc[2*nc+1], ah, bh[2], bh[3]);
            mma16816(dacc[2*nc+1], ah, bl[2], bl[3]);
            mma16816(dacc[2*nc+1], al, bh[2], bh[3]);
        }
    };

    // prologue: chunk 0
    {
        const uint4* srcW = (const uint4*)(g_wosplit + (size_t)(mt*16)*WTILE);
        uint4* dW = (uint4*)sW[0];
        dW[t] = srcW[t];
        dW[t + 256] = srcW[t + 256];
        if (t < 128) dW[t + 512] = srcW[t + 512];
        if (t < 128) {
            const uint4* s = (const uint4*)catsrc;
            uint4* dr = (uint4*)(sS[0] + brow*WROW + bpart*32);
            dr[0] = s[0]; dr[1] = s[1];
        }
    }
    __syncthreads();

    for (int kc = 0; kc < 16; ++kc) {
        int cur = kc & 1;
        bool more = (kc + 1 < 16);
        uint4 wa, wb, wc2, b0, b1;
        if (more) {
            const uint4* srcW = (const uint4*)(g_wosplit + (size_t)(mt*16 + kc + 1)*WTILE);
            wa = srcW[t];
            wb = srcW[t + 256];
            if (t < 128) {
                wc2 = srcW[t + 512];
                const uint4* s = (const uint4*)(catsrc + (kc + 1)*16);
                b0 = s[0]; b1 = s[1];
            }
        }
        domma(cur);
        if (more) {
            int nb = cur ^ 1;
            uint4* dW = (uint4*)sW[nb];
            dW[t] = wa;
            dW[t + 256] = wb;
            if (t < 128) {
                dW[t + 512] = wc2;
                uint4* dr = (uint4*)(sS[nb] + brow*WROW + bpart*32);
                dr[0] = b0; dr[1] = b1;
            }
        }
        __syncthreads();
    }

    // epilogue: write g_off (fp32, guarded o<648)
    int g = l >> 2, tq = l & 3;
    int o0 = mt*128 + w*16 + g;
    int o1 = o0 + 8;
    size_t base0 = ((size_t)b*NOFF + o0)*Pn + p0 + 2*tq;
    size_t base1 = base0 + (size_t)8*Pn;
    #pragma unroll
    for (int n = 0; n < 8; ++n) {
        if (o0 < NOFF)
            *(float2*)&g_off[base0 + n*8] = make_float2(dacc[n][0], dacc[n][1]);
        if (o1 < NOFF)
            *(float2*)&g_off[base1 + n*8] = make_float2(dacc[n][2], dacc[n][3]);
    }
}

// -------- fused deformable sampling + bf16-split tensor GEMM + ReLU ---------
// (unchanged from R8)
__global__ void __launch_bounds__(256, 2) k_dcn(float* __restrict__ out) {
    __shared__ __align__(16) uint8_t sW[2][WTILE];
    __shared__ __align__(16) uint8_t sS[2][STILE];

    int blk = blockIdx.x;               // Bn*(Pn/64) = 512
    int b  = blk >> 8;
    int p0 = (blk & 255) * 64;
    int t  = threadIdx.x;
    int w  = t >> 5, l = t & 31;
    int vv = t >> 2, q = t & 3;

    float dacc[8][4];
    #pragma unroll
    for (int n = 0; n < 8; ++n)
        #pragma unroll
        for (int j = 0; j < 4; ++j) dacc[n][j] = 0.f;

    const size_t offB = (size_t)b * NOFF * Pn;
    const float* upB  = g_up_cl + (size_t)b*Pn*CSn;
    const float* upg4 = upB + q*4;

    int p = p0 + vv;
    int dg = p >> 10, hg = (p >> 5) & 31, wg = p & 31;

    auto loadoffs = [&](int kk, float& z, float& y, float& x) {
        int g = kk / K3n, k = kk % K3n;
        int kz = k/9 - 1, ky = (k/3)%3 - 1, kx = k%3 - 1;
        size_t ob = offB + (size_t)(g*K3n + k)*3*Pn + p;
        z = dg + kz + g_off[ob];
        y = hg + ky + g_off[ob + Pn];
        x = wg + kx + g_off[ob + 2*Pn];
    };

    auto gather = [&](int kk, float z, float y, float x, int buf) {
        int g = kk / K3n;
        const float* upg = upg4 + g*CGn;

        float z0f = floorf(z), y0f = floorf(y), x0f = floorf(x);
        float fz = z - z0f, fy = y - y0f, fx = x - x0f;
        int z0 = (int)z0f, y0 = (int)y0f, x0 = (int)x0f;

        float wz0 = (z0   >= 0 && z0   < DDn) ? 1.f - fz : 0.f;
        float wz1 = (z0+1 >= 0 && z0+1 < DDn) ? fz       : 0.f;
        float wy0 = (y0   >= 0 && y0   < DHn) ? 1.f - fy : 0.f;
        float wy1 = (y0+1 >= 0 && y0+1 < DHn) ? fy       : 0.f;
        float wx0 = (x0   >= 0 && x0   < DWn) ? 1.f - fx : 0.f;
        float wx1 = (x0+1 >= 0 && x0+1 < DWn) ? fx       : 0.f;
        int zi0 = min(max(z0,   0), DDn-1) << 10;
        int zi1 = min(max(z0+1, 0), DDn-1) << 10;
        int yi0 = min(max(y0,   0), DHn-1) << 5;
        int yi1 = min(max(y0+1, 0), DHn-1) << 5;
        int xi0 = min(max(x0,   0), DWn-1);
        int xi1 = min(max(x0+1, 0), DWn-1);
        float w00 = wz0*wy0, w01 = wz0*wy1, w10 = wz1*wy0, w11 = wz1*wy1;
        int   i00 = zi0+yi0, i01 = zi0+yi1, i10 = zi1+yi0, i11 = zi1+yi1;

        float4 sa = make_float4(0.f, 0.f, 0.f, 0.f);
        #pragma unroll
        for (int cnr = 0; cnr < 8; ++cnr) {
            float wzy = (cnr>>2) ? ((cnr>>1)&1 ? w11 : w10) : ((cnr>>1)&1 ? w01 : w00);
            int   izy = (cnr>>2) ? ((cnr>>1)&1 ? i11 : i10) : ((cnr>>1)&1 ? i01 : i00);
            float wt  = wzy * ((cnr&1) ? wx1 : wx0);
            int   ci  = izy + ((cnr&1) ? xi1 : xi0);
            float4 v = *(const float4*)(upg + (size_t)ci*CSn);
            sa.x += wt*v.x; sa.y += wt*v.y; sa.z += wt*v.z; sa.w += wt*v.w;
        }
        __nv_bfloat16 h0 = __float2bfloat16(sa.x);
        __nv_bfloat16 h1 = __float2bfloat16(sa.y);
        __nv_bfloat16 h2 = __float2bfloat16(sa.z);
        __nv_bfloat16 h3 = __float2bfloat16(sa.w);
        __nv_bfloat16 l0 = __float2bfloat16(sa.x - __bfloat162float(h0));
        __nv_bfloat16 l1 = __float2bfloat16(sa.y - __bfloat162float(h1));
        __nv_bfloat16 l2 = __float2bfloat16(sa.z - __bfloat162float(h2));
        __nv_bfloat16 l3 = __float2bfloat16(sa.w - __bfloat162float(h3));
        uint8_t* rowp = sS[buf] + vv*WROW + q*8;
        *(uint2*)rowp        = make_uint2(packbf(h0,h1), packbf(h2,h3));
        *(uint2*)(rowp + 32) = make_uint2(packbf(l0,l1), packbf(l2,l3));
    };

    auto domma = [&](int buf) {
        uint32_t sWb = (uint32_t)__cvta_generic_to_shared(&sW[buf][0]);
        uint32_t sSb = (uint32_t)__cvta_generic_to_shared(&sS[buf][0]);
        uint32_t aaddr = sWb + (w*16 + (l & 15))*WROW + (l >> 4)*16;
        uint32_t ah[4], al[4];
        ldsm4(ah, aaddr);
        ldsm4(al, aaddr + 32);
        uint32_t brow = 8*(l >> 4) + (l & 7);
        uint32_t bcol = ((l >> 3) & 1)*16;
        #pragma unroll
        for (int nc = 0; nc < 4; ++nc) {
            uint32_t baddr = sSb + (nc*16 + brow)*WROW + bcol;
            uint32_t bh[4], bl[4];
            ldsm4(bh, baddr);
            ldsm4(bl, baddr + 32);
            mma16816(dacc[2*nc  ], ah, bh[0], bh[1]);
            mma16816(dacc[2*nc  ], ah, bl[0], bl[1]);
            mma16816(dacc[2*nc  ], al, bh[0], bh[1]);
            mma16816(dacc[2*nc+1], ah, bh[2], bh[3]);
            mma16816(dacc[2*nc+1], ah, bl[2], bl[3]);
            mma16816(dacc[2*nc+1], al, bh[2], bh[3]);
        }
    };

    {
        float z, y, x;
        loadoffs(0, z, y, x);
        gather(0, z, y, x, 0);
        const uint4* srcW = (const uint4*)(g_wsplit);
        uint4* dstW = (uint4*)sW[0];
        dstW[t] = srcW[t];
        dstW[t + 256] = srcW[t + 256];
        if (t < WTILE/16 - 512) dstW[t + 512] = srcW[t + 512];
    }
    __syncthreads();

    for (int kk = 0; kk < NTAP; ++kk) {
        int cur = kk & 1;

        float z, y, x;
        uint4 wr0, wr1, wr2;
        bool more = (kk + 1 < NTAP);
        if (more) {
            loadoffs(kk + 1, z, y, x);
            const uint4* srcW = (const uint4*)(g_wsplit + (size_t)(kk+1)*WTILE);
            wr0 = srcW[t];
            wr1 = srcW[t + 256];
            if (t < WTILE/16 - 512) wr2 = srcW[t + 512];
        }

        domma(cur);

        if (more) {
            int nb = cur ^ 1;
            uint4* dstW = (uint4*)sW[nb];
            dstW[t] = wr0;
            dstW[t + 256] = wr1;
            if (t < WTILE/16 - 512) dstW[t + 512] = wr2;
            gather(kk + 1, z, y, x, nb);
        }
        __syncthreads();
    }

    int g = l >> 2, tq = l & 3;
    size_t base0 = ((size_t)b*CDn + w*16 + g)*Pn + p0 + 2*tq;
    size_t base1 = base0 + (size_t)8*Pn;
    #pragma unroll
    for (int n = 0; n < 8; ++n) {
        float2 v0 = make_float2(fmaxf(dacc[n][0], 0.f), fmaxf(dacc[n][1], 0.f));
        float2 v1 = make_float2(fmaxf(dacc[n][2], 0.f), fmaxf(dacc[n][3], 0.f));
        *(float2*)&out[base0 + n*8] = v0;
        *(float2*)&out[base1 + n*8] = v1;
    }
}

extern "C" void kernel_launch(void* const* d_in, const int* in_sizes, int n_in,
                              void* d_out, int out_size) {
    const float* src  = (const float*)d_in[0];   // feat_1x_src [2,128,8,16,16]
    const float* dst  = (const float*)d_in[1];   // feat_2x_dst [2,128,16,32,32]
    const float* woff = (const float*)d_in[2];   // w_offset [648,256]
    const float* wdcn = (const float*)d_in[3];   // w_dcn [128,128,3,3,3]
    float* out = (float*)d_out;

    const int NPREP = Bn*SDn*SHn*SWn*CSn + NTAP*128*CGn + MTILES*128*256;
    k_prep     <<<(NPREP + 255)/256, 256>>>(src, woff, wdcn);
    k_upsample <<<Bn*Pn, 128>>>();
    k_cat      <<<Bn*(Pn/32), 256>>>(dst);
    k_offmma   <<<Bn*MTILES*(Pn/64), 256>>>();
    k_dcn      <<<Bn*(Pn/64), 256>>>(out);
}

// round 10
// speedup vs baseline: 2.3512x; 1.1251x over previous
#include <cuda_runtime.h>
#include <cuda_bf16.h>
#include <cstdint>

#define Bn 2
#define CSn 128
#define CDn 128
#define SDn 8
#define SHn 16
#define SWn 16
#define DDn 16
#define DHn 32
#define DWn 32
#define Pn  (DDn*DHn*DWn)      /* 16384 */
#define Gn 8
#define K3n 27
#define CGn 16                 /* CS/G */
#define NOFF (K3n*3*Gn)        /* 648 */
#define NTAP (Gn*K3n)          /* 216 */
#define WROW 80                /* padded row bytes of A/B smem tiles */
#define WTILE (128*WROW)       /* 10240 B per weight tile */
#define STILE (64*WROW)        /* 5120 B per sample tile */
#define MTILES 6               /* ceil(648/128) m-tiles for offset GEMM */
#define DCN_SMEM (4*WTILE + 4*STILE)   /* 61440 B */

// ---------------- tensor-core helpers ---------------------------------------
__device__ __forceinline__ void ldsm4(uint32_t* r, uint32_t addr) {
    asm volatile("ldmatrix.sync.aligned.m8n8.x4.shared.b16 {%0,%1,%2,%3},[%4];"
        : "=r"(r[0]), "=r"(r[1]), "=r"(r[2]), "=r"(r[3]) : "r"(addr));
}
__device__ __forceinline__ void mma16816(float* d, const uint32_t* a,
                                         uint32_t b0, uint32_t b1) {
    asm volatile(
        "mma.sync.aligned.m16n8k16.row.col.f32.bf16.bf16.f32 "
        "{%0,%1,%2,%3},{%4,%5,%6,%7},{%8,%9},{%0,%1,%2,%3};"
        : "+f"(d[0]), "+f"(d[1]), "+f"(d[2]), "+f"(d[3])
        : "r"(a[0]), "r"(a[1]), "r"(a[2]), "r"(a[3]), "r"(b0), "r"(b1));
}
__device__ __forceinline__ uint32_t packbf(__nv_bfloat16 a, __nv_bfloat16 b) {
    __nv_bfloat162 t = __halves2bfloat162(a, b);
    return *(uint32_t*)&t;
}

// -------- device scratch ----------------------------------------------------
__device__ float g_src_cl[Bn*SDn*SHn*SWn*CSn];   // [b][z][y][x][c]
__device__ float g_up_cl[Bn*Pn*CSn];             // [b][p][c]
__device__ float g_off[Bn*NOFF*Pn];              // [b][o][p]
__device__ __align__(16) uint8_t g_wsplit[(size_t)NTAP*WTILE];       // dcn W hi/lo
__device__ __align__(16) uint8_t g_wosplit[(size_t)MTILES*16*WTILE]; // offset W hi/lo
__device__ __align__(16) __nv_bfloat16 g_cath[(size_t)Bn*Pn*256];    // cat hi [b][p][c]
__device__ __align__(16) __nv_bfloat16 g_catl[(size_t)Bn*Pn*256];    // cat lo

// -------- prep: transposes + bf16 weight splits ------------------------------
__global__ void k_prep(const float* __restrict__ src,
                       const float* __restrict__ woff,
                       const float* __restrict__ wdcn) {
    int i = blockIdx.x * blockDim.x + threadIdx.x;
    const int N1 = Bn*SDn*SHn*SWn*CSn;    // 524288
    const int N3 = NTAP*128*CGn;          // 442368
    const int N4 = MTILES*128*256;        // 196608 (768 o x 256 c)
    if (i < N1) {
        int c = i % CSn;
        int s = (i / CSn) % (SDn*SHn*SWn);
        int b = i / (CSn*SDn*SHn*SWn);
        g_src_cl[i] = src[(b*CSn + c)*(SDn*SHn*SWn) + s];
    } else if (i < N1 + N3) {
        int j = i - N1;
        int cg = j % CGn;
        int o  = (j / CGn) % 128;
        int kk = j / (CGn*128);
        int g = kk / K3n, k = kk % K3n;
        float wv = wdcn[((o*CSn) + g*CGn + cg)*K3n + k];
        __nv_bfloat16 hb = __float2bfloat16(wv);
        __nv_bfloat16 lb = __float2bfloat16(wv - __bfloat162float(hb));
        uint8_t* row = g_wsplit + (size_t)kk*WTILE + o*WROW;
        *(__nv_bfloat16*)(row + cg*2)      = hb;
        *(__nv_bfloat16*)(row + 32 + cg*2) = lb;
    } else if (i < N1 + N3 + N4) {
        int j = i - N1 - N3;
        int c = j % 256;
        int o = j / 256;                  // 0..767 (padded)
        float wv = (o < NOFF) ? woff[o*256 + c] : 0.f;
        __nv_bfloat16 hb = __float2bfloat16(wv);
        __nv_bfloat16 lb = __float2bfloat16(wv - __bfloat162float(hb));
        int mt = o >> 7, kc = c >> 4;
        uint8_t* row = g_wosplit + (size_t)(mt*16 + kc)*WTILE + (o & 127)*WROW;
        *(__nv_bfloat16*)(row + (c & 15)*2)      = hb;
        *(__nv_bfloat16*)(row + 32 + (c & 15)*2) = lb;
    }
}

// -------- trilinear 2x upsample ----------------------------------------------
__global__ void k_upsample() {
    int bp = blockIdx.x;                 // Bn*Pn blocks
    int b = bp / Pn;
    int p = bp % Pn;
    int d = p >> 10, h = (p >> 5) & 31, w = p & 31;

    float zc = d*0.5f - 0.25f, yc = h*0.5f - 0.25f, xc = w*0.5f - 0.25f;
    int zf = (int)floorf(zc), yf = (int)floorf(yc), xf = (int)floorf(xc);
    float fz = zc - zf, fy = yc - yf, fx = xc - xf;
    int z0 = min(max(zf,     0), SDn-1), z1 = min(max(zf + 1, 0), SDn-1);
    int y0 = min(max(yf,     0), SHn-1), y1 = min(max(yf + 1, 0), SHn-1);
    int x0 = min(max(xf,     0), SWn-1), x1 = min(max(xf + 1, 0), SWn-1);

    const float* base = g_src_cl + (size_t)b * (SDn*SHn*SWn) * CSn;
    int c = threadIdx.x;  // 128

    float v000 = base[(z0*256 + y0*16 + x0)*CSn + c];
    float v001 = base[(z0*256 + y0*16 + x1)*CSn + c];
    float v010 = base[(z0*256 + y1*16 + x0)*CSn + c];
    float v011 = base[(z0*256 + y1*16 + x1)*CSn + c];
    float v100 = base[(z1*256 + y0*16 + x0)*CSn + c];
    float v101 = base[(z1*256 + y0*16 + x1)*CSn + c];
    float v110 = base[(z1*256 + y1*16 + x0)*CSn + c];
    float v111 = base[(z1*256 + y1*16 + x1)*CSn + c];

    float r0 = (1.f-fy)*((1.f-fx)*v000 + fx*v001) + fy*((1.f-fx)*v010 + fx*v011);
    float r1 = (1.f-fy)*((1.f-fx)*v100 + fx*v101) + fy*((1.f-fx)*v110 + fx*v111);
    g_up_cl[((size_t)b*Pn + p)*CSn + c] = (1.f-fz)*r0 + fz*r1;
}

// -------- build pre-split bf16 cat image [b][p][256c] ------------------------
__global__ void __launch_bounds__(256) k_cat(const float* __restrict__ dst) {
    __shared__ float cat_s[256*33];     // padded to kill bank conflicts
    int blk = blockIdx.x;               // Bn*(Pn/32)
    int b  = blk / (Pn/32);
    int p0 = (blk % (Pn/32)) * 32;
    int t = threadIdx.x;

    for (int i = t; i < 128*32; i += 256) {
        int c = i >> 5, v = i & 31;
        cat_s[c*33 + v] = dst[((size_t)b*CDn + c)*Pn + p0 + v];
    }
    for (int i = t; i < 32*128; i += 256) {
        int v = i >> 7, c = i & 127;
        cat_s[(128 + c)*33 + v] = 2.0f * g_up_cl[((size_t)b*Pn + p0 + v)*CSn + c];
    }
    __syncthreads();

    int v = t & 31, cg = t >> 5;        // 8 groups of 32 channels
    uint32_t oh[16], ol[16];
    #pragma unroll
    for (int j = 0; j < 16; ++j) {
        float f0 = cat_s[(cg*32 + 2*j    )*33 + v];
        float f1 = cat_s[(cg*32 + 2*j + 1)*33 + v];
        __nv_bfloat16 h0 = __float2bfloat16(f0);
        __nv_bfloat16 h1 = __float2bfloat16(f1);
        __nv_bfloat16 l0 = __float2bfloat16(f0 - __bfloat162float(h0));
        __nv_bfloat16 l1 = __float2bfloat16(f1 - __bfloat162float(h1));
        oh[j] = packbf(h0, h1);
        ol[j] = packbf(l0, l1);
    }
    size_t base = ((size_t)b*Pn + p0 + v)*256 + cg*32;
    uint4* dh = (uint4*)&g_cath[base];
    uint4* dl = (uint4*)&g_catl[base];
    #pragma unroll
    for (int j = 0; j < 4; ++j) {
        dh[j] = make_uint4(oh[4*j], oh[4*j+1], oh[4*j+2], oh[4*j+3]);
        dl[j] = make_uint4(ol[4*j], ol[4*j+1], ol[4*j+2], ol[4*j+3]);
    }
}

// -------- offset GEMM on tensor cores: g_off[b,o,p] --------------------------
__global__ void __launch_bounds__(256, 2) k_offmma() {
    __shared__ __align__(16) uint8_t sW[2][WTILE];   // 20KB
    __shared__ __align__(16) uint8_t sS[2][STILE];   // 10KB

    int blk = blockIdx.x;               // Bn*MTILES*(Pn/64) = 3072
    int b  = blk / (MTILES*256);
    int r  = blk % (MTILES*256);
    int mt = r / 256;
    int p0 = (r % 256) * 64;
    int t  = threadIdx.x;
    int w  = t >> 5, l = t & 31;

    float dacc[8][4];
    #pragma unroll
    for (int n = 0; n < 8; ++n)
        #pragma unroll
        for (int j = 0; j < 4; ++j) dacc[n][j] = 0.f;

    int brow = t >> 1, bpart = t & 1;   // B staging map (t<128)
    const __nv_bfloat16* catsrc = (bpart ? g_catl : g_cath)
                                + ((size_t)b*Pn + p0 + brow)*256;

    auto domma = [&](int buf) {
        uint32_t sWb = (uint32_t)__cvta_generic_to_shared(&sW[buf][0]);
        uint32_t sSb = (uint32_t)__cvta_generic_to_shared(&sS[buf][0]);
        uint32_t aaddr = sWb + (w*16 + (l & 15))*WROW + (l >> 4)*16;
        uint32_t ah[4], al[4];
        ldsm4(ah, aaddr);
        ldsm4(al, aaddr + 32);
        uint32_t br = 8*(l >> 4) + (l & 7);
        uint32_t bc = ((l >> 3) & 1)*16;
        #pragma unroll
        for (int nc = 0; nc < 4; ++nc) {
            uint32_t baddr = sSb + (nc*16 + br)*WROW + bc;
            uint32_t bh[4], bl[4];
            ldsm4(bh, baddr);
            ldsm4(bl, baddr + 32);
            mma16816(dacc[2*nc  ], ah, bh[0], bh[1]);
            mma16816(dacc[2*nc  ], ah, bl[0], bl[1]);
            mma16816(dacc[2*nc  ], al, bh[0], bh[1]);
            mma16816(dacc[2*nc+1], ah, bh[2], bh[3]);
            mma16816(dacc[2*nc+1], ah, bl[2], bl[3]);
            mma16816(dacc[2*nc+1], al, bh[2], bh[3]);
        }
    };

    {
        const uint4* srcW = (const uint4*)(g_wosplit + (size_t)(mt*16)*WTILE);
        uint4* dW = (uint4*)sW[0];
        dW[t] = srcW[t];
        dW[t + 256] = srcW[t + 256];
        if (t < 128) dW[t + 512] = srcW[t + 512];
        if (t < 128) {
            const uint4* s = (const uint4*)catsrc;
            uint4* dr = (uint4*)(sS[0] + brow*WROW + bpart*32);
            dr[0] = s[0]; dr[1] = s[1];
        }
    }
    __syncthreads();

    for (int kc = 0; kc < 16; ++kc) {
        int cur = kc & 1;
        bool more = (kc + 1 < 16);
        uint4 wa, wb, wc2, b0, b1;
        if (more) {
            const uint4* srcW = (const uint4*)(g_wosplit + (size_t)(mt*16 + kc + 1)*WTILE);
            wa = srcW[t];
            wb = srcW[t + 256];
            if (t < 128) {
                wc2 = srcW[t + 512];
                const uint4* s = (const uint4*)(catsrc + (kc + 1)*16);
                b0 = s[0]; b1 = s[1];
            }
        }
        domma(cur);
        if (more) {
            int nb = cur ^ 1;
            uint4* dW = (uint4*)sW[nb];
            dW[t] = wa;
            dW[t + 256] = wb;
            if (t < 128) {
                dW[t + 512] = wc2;
                uint4* dr = (uint4*)(sS[nb] + brow*WROW + bpart*32);
                dr[0] = b0; dr[1] = b1;
            }
        }
        __syncthreads();
    }

    int g = l >> 2, tq = l & 3;
    int o0 = mt*128 + w*16 + g;
    int o1 = o0 + 8;
    size_t base0 = ((size_t)b*NOFF + o0)*Pn + p0 + 2*tq;
    size_t base1 = base0 + (size_t)8*Pn;
    #pragma unroll
    for (int n = 0; n < 8; ++n) {
        if (o0 < NOFF)
            *(float2*)&g_off[base0 + n*8] = make_float2(dacc[n][0], dacc[n][1]);
        if (o1 < NOFF)
            *(float2*)&g_off[base1 + n*8] = make_float2(dacc[n][2], dacc[n][3]);
    }
}

// -------- fused deformable sampling + bf16-split tensor GEMM + ReLU ---------
// block: 64 voxels, 256 threads, 2 CTAs/SM; 4-buffer ring, 2 taps per barrier.
__global__ void __launch_bounds__(256, 2) k_dcn(float* __restrict__ out) {
    extern __shared__ __align__(16) uint8_t dyn[];
    uint8_t* sW = dyn;                  // 4 x WTILE
    uint8_t* sS = dyn + 4*WTILE;        // 4 x STILE

    int blk = blockIdx.x;               // Bn*(Pn/64) = 512
    int b  = blk >> 8;
    int p0 = (blk & 255) * 64;
    int t  = threadIdx.x;
    int w  = t >> 5, l = t & 31;
    int vv = t >> 2, q = t & 3;

    float dacc[8][4];
    #pragma unroll
    for (int n = 0; n < 8; ++n)
        #pragma unroll
        for (int j = 0; j < 4; ++j) dacc[n][j] = 0.f;

    const size_t offB = (size_t)b * NOFF * Pn;
    const float* upB  = g_up_cl + (size_t)b*Pn*CSn;
    const float* upg4 = upB + q*4;

    int p = p0 + vv;
    int dg = p >> 10, hg = (p >> 5) & 31, wg = p & 31;

    auto loadoffs = [&](int kk, float& z, float& y, float& x) {
        int g = kk / K3n, k = kk % K3n;
        int kz = k/9 - 1, ky = (k/3)%3 - 1, kx = k%3 - 1;
        size_t ob = offB + (size_t)(g*K3n + k)*3*Pn + p;
        z = dg + kz + g_off[ob];
        y = hg + ky + g_off[ob + Pn];
        x = wg + kx + g_off[ob + 2*Pn];
    };

    auto wpre = [&](int kk, uint4& r0, uint4& r1, uint4& r2) {
        const uint4* srcW = (const uint4*)(g_wsplit + (size_t)kk*WTILE);
        r0 = srcW[t];
        r1 = srcW[t + 256];
        if (t < 128) r2 = srcW[t + 512];
    };
    auto wst = [&](int buf, uint4 r0, uint4 r1, uint4 r2) {
        uint4* dstW = (uint4*)(sW + buf*WTILE);
        dstW[t] = r0;
        dstW[t + 256] = r1;
        if (t < 128) dstW[t + 512] = r2;
    };

    auto gather = [&](int kk, float z, float y, float x, int buf) {
        int g = kk / K3n;
        const float* upg = upg4 + g*CGn;

        float z0f = floorf(z), y0f = floorf(y), x0f = floorf(x);
        float fz = z - z0f, fy = y - y0f, fx = x - x0f;
        int z0 = (int)z0f, y0 = (int)y0f, x0 = (int)x0f;

        float wz0 = (z0   >= 0 && z0   < DDn) ? 1.f - fz : 0.f;
        float wz1 = (z0+1 >= 0 && z0+1 < DDn) ? fz       : 0.f;
        float wy0 = (y0   >= 0 && y0   < DHn) ? 1.f - fy : 0.f;
        float wy1 = (y0+1 >= 0 && y0+1 < DHn) ? fy       : 0.f;
        float wx0 = (x0   >= 0 && x0   < DWn) ? 1.f - fx : 0.f;
        float wx1 = (x0+1 >= 0 && x0+1 < DWn) ? fx       : 0.f;
        int zi0 = min(max(z0,   0), DDn-1) << 10;
        int zi1 = min(max(z0+1, 0), DDn-1) << 10;
        int yi0 = min(max(y0,   0), DHn-1) << 5;
        int yi1 = min(max(y0+1, 0), DHn-1) << 5;
        int xi0 = min(max(x0,   0), DWn-1);
        int xi1 = min(max(x0+1, 0), DWn-1);
        float w00 = wz0*wy0, w01 = wz0*wy1, w10 = wz1*wy0, w11 = wz1*wy1;
        int   i00 = zi0+yi0, i01 = zi0+yi1, i10 = zi1+yi0, i11 = zi1+yi1;

        float4 sa = make_float4(0.f, 0.f, 0.f, 0.f);
        #pragma unroll
        for (int cnr = 0; cnr < 8; ++cnr) {
            float wzy = (cnr>>2) ? ((cnr>>1)&1 ? w11 : w10) : ((cnr>>1)&1 ? w01 : w00);
            int   izy = (cnr>>2) ? ((cnr>>1)&1 ? i11 : i10) : ((cnr>>1)&1 ? i01 : i00);
            float wt  = wzy * ((cnr&1) ? wx1 : wx0);
            int   ci  = izy + ((cnr&1) ? xi1 : xi0);
            float4 v = *(const float4*)(upg + (size_t)ci*CSn);
            sa.x += wt*v.x; sa.y += wt*v.y; sa.z += wt*v.z; sa.w += wt*v.w;
        }
        __nv_bfloat16 h0 = __float2bfloat16(sa.x);
        __nv_bfloat16 h1 = __float2bfloat16(sa.y);
        __nv_bfloat16 h2 = __float2bfloat16(sa.z);
        __nv_bfloat16 h3 = __float2bfloat16(sa.w);
        __nv_bfloat16 l0 = __float2bfloat16(sa.x - __bfloat162float(h0));
        __nv_bfloat16 l1 = __float2bfloat16(sa.y - __bfloat162float(h1));
        __nv_bfloat16 l2 = __float2bfloat16(sa.z - __bfloat162float(h2));
        __nv_bfloat16 l3 = __float2bfloat16(sa.w - __bfloat162float(h3));
        uint8_t* rowp = sS + buf*STILE + vv*WROW + q*8;
        *(uint2*)rowp        = make_uint2(packbf(h0,h1), packbf(h2,h3));
        *(uint2*)(rowp + 32) = make_uint2(packbf(l0,l1), packbf(l2,l3));
    };

    auto domma = [&](int buf) {
        uint32_t sWb = (uint32_t)__cvta_generic_to_shared(sW + buf*WTILE);
        uint32_t sSb = (uint32_t)__cvta_generic_to_shared(sS + buf*STILE);
        uint32_t aaddr = sWb + (w*16 + (l & 15))*WROW + (l >> 4)*16;
        uint32_t ah[4], al[4];
        ldsm4(ah, aaddr);
        ldsm4(al, aaddr + 32);
        uint32_t brow = 8*(l >> 4) + (l & 7);
        uint32_t bcol = ((l >> 3) & 1)*16;
        #pragma unroll
        for (int nc = 0; nc < 4; ++nc) {
            uint32_t baddr = sSb + (nc*16 + brow)*WROW + bcol;
            uint32_t bh[4], bl[4];
            ldsm4(bh, baddr);
            ldsm4(bl, baddr + 32);
            mma16816(dacc[2*nc  ], ah, bh[0], bh[1]);
            mma16816(dacc[2*nc  ], ah, bl[0], bl[1]);
            mma16816(dacc[2*nc  ], al, bh[0], bh[1]);
            mma16816(dacc[2*nc+1], ah, bh[2], bh[3]);
            mma16816(dacc[2*nc+1], ah, bl[2], bl[3]);
            mma16816(dacc[2*nc+1], al, bh[2], bh[3]);
        }
    };

    // ---- prologue: taps 0 and 1 ----
    {
        float z0, y0, x0, z1, y1, x1;
        loadoffs(0, z0, y0, x0);
        loadoffs(1, z1, y1, x1);
        uint4 r0, r1, r2;
        wpre(0, r0, r1, r2); wst(0, r0, r1, r2);
        wpre(1, r0, r1, r2); wst(1, r0, r1, r2);
        gather(0, z0, y0, x0, 0);
        gather(1, z1, y1, x1, 1);
    }
    __syncthreads();

    // ---- main loop: 2 taps per barrier ----
    for (int kk = 0; kk < NTAP; kk += 2) {
        bool more = (kk + 2 < NTAP);
        float z2, y2, x2, z3, y3, x3;
        uint4 r0, r1, r2;
        if (more) {
            loadoffs(kk + 2, z2, y2, x2);
            loadoffs(kk + 3, z3, y3, x3);
            wpre(kk + 2, r0, r1, r2);
        }

        domma(kk & 3);

        if (more) {
            wst((kk + 2) & 3, r0, r1, r2);
            wpre(kk + 3, r0, r1, r2);
        }

        domma((kk + 1) & 3);

        if (more) {
            wst((kk + 3) & 3, r0, r1, r2);
            gather(kk + 2, z2, y2, x2, (kk + 2) & 3);
            gather(kk + 3, z3, y3, x3, (kk + 3) & 3);
        }
        __syncthreads();
    }

    // ---- epilogue: ReLU + STG.64 ----
    int g = l >> 2, tq = l & 3;
    size_t base0 = ((size_t)b*CDn + w*16 + g)*Pn + p0 + 2*tq;
    size_t base1 = base0 + (size_t)8*Pn;
    #pragma unroll
    for (int n = 0; n < 8; ++n) {
        float2 v0 = make_float2(fmaxf(dacc[n][0], 0.f), fmaxf(dacc[n][1], 0.f));
        float2 v1 = make_float2(fmaxf(dacc[n][2], 0.f), fmaxf(dacc[n][3], 0.f));
        *(float2*)&out[base0 + n*8] = v0;
        *(float2*)&out[base1 + n*8] = v1;
    }
}

extern "C" void kernel_launch(void* const* d_in, const int* in_sizes, int n_in,
                              void* d_out, int out_size) {
    const float* src  = (const float*)d_in[0];   // feat_1x_src [2,128,8,16,16]
    const float* dst  = (const float*)d_in[1];   // feat_2x_dst [2,128,16,32,32]
    const float* woff = (const float*)d_in[2];   // w_offset [648,256]
    const float* wdcn = (const float*)d_in[3];   // w_dcn [128,128,3,3,3]
    float* out = (float*)d_out;

    cudaFuncSetAttribute(k_dcn, cudaFuncAttributeMaxDynamicSharedMemorySize,
                         DCN_SMEM);

    const int NPREP = Bn*SDn*SHn*SWn*CSn + NTAP*128*CGn + MTILES*128*256;
    k_prep     <<<(NPREP + 255)/256, 256>>>(src, woff, wdcn);
    k_upsample <<<Bn*Pn, 128>>>();
    k_cat      <<<Bn*(Pn/32), 256>>>(dst);
    k_offmma   <<<Bn*MTILES*(Pn/64), 256>>>();
    k_dcn      <<<Bn*(Pn/64), 256, DCN_SMEM>>>(out);
}